// round 12
// baseline (speedup 1.0000x reference)
#include <cuda_runtime.h>
#include <cuda_fp16.h>
#include <cstdint>

#define S_LEN   2048
#define DMODEL  1024
#define BATCH   2
#define NHEADS  16
#define HDIM    64
#define QKV_LD  3072
#define NKTILES (S_LEN / 64)
#define MROWS   (BATCH * S_LEN)   // 4096
#define MBLK    (MROWS / 128)     // 32
#define KIT     (DMODEL / 32)     // 32

__device__ float g_q[(size_t)MROWS * DMODEL];           // dense Q fp32
__device__ uint2 g_kfrag[(size_t)BATCH * NHEADS * NKTILES * 1024];  // K single fp16
__device__ uint4 g_vfrag[(size_t)BATCH * NHEADS * NKTILES * 1024];  // V hi/lo
__device__ uint4 g_wqkv_frag[(size_t)(QKV_LD / 128) * KIT * 1024];
__device__ uint4 g_wout_frag[(size_t)(DMODEL / 128) * KIT * 1024];
__device__ uint4 g_atok_frag[(size_t)MBLK * KIT * 512];
__device__ uint4 g_actx_frag[(size_t)MBLK * KIT * 512];

// ---------------------------------------------------------------------------
__device__ __forceinline__ void mma_f16(float* d, const uint32_t* a, const uint32_t* b) {
    asm volatile(
        "mma.sync.aligned.m16n8k16.row.col.f32.f16.f16.f32 "
        "{%0,%1,%2,%3}, {%4,%5,%6,%7}, {%8,%9}, {%0,%1,%2,%3};\n"
        : "+f"(d[0]), "+f"(d[1]), "+f"(d[2]), "+f"(d[3])
        : "r"(a[0]), "r"(a[1]), "r"(a[2]), "r"(a[3]), "r"(b[0]), "r"(b[1]));
}

__device__ __forceinline__ void split2h(float x, __half& hi, __half& lo) {
    hi = __float2half_rn(x);
    lo = __float2half_rn(x - __half2float(hi));
}

__device__ __forceinline__ uint32_t pack2h(float x, float y) {
    __half2 h = __floats2half2_rn(x, y);
    return *(uint32_t*)&h;
}

__device__ __forceinline__ void cp_async16(void* smem_ptr, const void* gptr) {
    uint32_t sa = (uint32_t)__cvta_generic_to_shared(smem_ptr);
    asm volatile("cp.async.cg.shared.global [%0], [%1], 16;\n" :: "r"(sa), "l"(gptr));
}
__device__ __forceinline__ void cp_commit() {
    asm volatile("cp.async.commit_group;\n");
}
template <int N>
__device__ __forceinline__ void cp_wait() {
    asm volatile("cp.async.wait_group %0;\n" :: "n"(N));
}

__device__ __forceinline__ bool in_ns(int s, int pos) {
    return (unsigned)(s - pos) < 8u;
}

// ---------------------------------------------------------------------------
// Combined presplit: [0,768) W_qkv B-frags, [768,1024) W_out B-frags,
// [1024,2048) tokens A-frags.
// ---------------------------------------------------------------------------
__global__ void __launch_bounds__(256) presplit_all_kernel(
    const float* __restrict__ tokens, const float* __restrict__ W_qkv,
    const float* __restrict__ W_out)
{
    const int bid = blockIdx.x;
    if (bid < 1024) {
        const float* W;
        uint4* out;
        int N, j;
        if (bid < 768) { W = W_qkv; out = g_wqkv_frag; N = QKV_LD; j = bid; }
        else           { W = W_out; out = g_wout_frag; N = DMODEL; j = bid - 768; }
        const int it = j & 31;
        const int nb = j >> 5;
        uint4* chunk = out + ((size_t)nb * KIT + it) * 1024;
#pragma unroll
        for (int i = 0; i < 4; i++) {
            const int s    = threadIdx.x + i * 256;
            const int lane = s & 31;
            const int n8   = (s >> 5) & 15;
            const int ks   = s >> 9;
            const int n = nb * 128 + n8 * 8 + (lane >> 2);
            const int k = it * 32 + ks * 16 + (lane & 3) * 2;
            const float b0 = W[(size_t)k * N + n];
            const float b1 = W[(size_t)(k + 1) * N + n];
            const float b2 = W[(size_t)(k + 8) * N + n];
            const float b3 = W[(size_t)(k + 9) * N + n];
            __half h0, l0, h1, l1, h2, l2, h3, l3;
            split2h(b0, h0, l0); split2h(b1, h1, l1);
            split2h(b2, h2, l2); split2h(b3, h3, l3);
            __half2 whi0(h0, h1), whi1(h2, h3), wlo0(l0, l1), wlo1(l2, l3);
            chunk[s] = make_uint4(*(uint32_t*)&whi0, *(uint32_t*)&whi1,
                                  *(uint32_t*)&wlo0, *(uint32_t*)&wlo1);
        }
    } else {
        const int j  = bid - 1024;
        const int it = j & 31;
        const int mb = j >> 5;
        uint4* chunk = g_atok_frag + ((size_t)mb * KIT + it) * 512;
#pragma unroll
        for (int i = 0; i < 2; i++) {
            const int s    = threadIdx.x + i * 256;
            const int lane = s & 31;
            const int mt   = (s >> 5) & 7;
            const int ks   = s >> 8;
            const int m = mb * 128 + mt * 16 + (lane >> 2);
            const int k = it * 32 + ks * 16 + (lane & 3) * 2;
            const float2 r0 = *(const float2*)&tokens[(size_t)m * DMODEL + k];
            const float2 r1 = *(const float2*)&tokens[(size_t)(m + 8) * DMODEL + k];
            const float2 r2 = *(const float2*)&tokens[(size_t)m * DMODEL + k + 8];
            const float2 r3 = *(const float2*)&tokens[(size_t)(m + 8) * DMODEL + k + 8];
            chunk[s] = make_uint4(pack2h(r0.x, r0.y), pack2h(r1.x, r1.y),
                                  pack2h(r2.x, r2.y), pack2h(r3.x, r3.y));
        }
    }
}

// ---------------------------------------------------------------------------
// QKV frag GEMM + fused frag emission (K single fp16, V hi/lo) + ns blocks.
// ---------------------------------------------------------------------------
__global__ void __launch_bounds__(256) gemm_qkv_kernel(
    const float* __restrict__ bias, const float* __restrict__ tokens,
    const int* __restrict__ seqc,
    const float* __restrict__ Wq, const float* __restrict__ bq,
    const float* __restrict__ Wk, const float* __restrict__ bk,
    const float* __restrict__ Wv, const float* __restrict__ bv)
{
    extern __shared__ uint4 dyn[];

    if (blockIdx.x >= 768) {
        float* st = (float*)dyn;
        const int bid2 = blockIdx.x - 768;
        const int mat = bid2 >> 4;
        const int b   = (bid2 >> 3) & 1;
        const int n   = bid2 & 7;
        const int pos = *seqc;
        const int row = pos + n;
        if (pos < 0 || row < 0 || row >= S_LEN) return;

        const float* W; const float* bb;
        if (mat == 0)      { W = Wq; bb = bq; }
        else if (mat == 1) { W = Wk; bb = bk; }
        else               { W = Wv; bb = bv; }
        W  += (size_t)n * DMODEL * DMODEL;
        bb += n * DMODEL;

        const float* trow = tokens + ((size_t)b * S_LEN + row) * DMODEL;
        const int tid = threadIdx.x;
        *(float4*)&st[tid * 4] = *(const float4*)&trow[tid * 4];
        __syncthreads();

        float acc[4];
#pragma unroll
        for (int j = 0; j < 4; j++) acc[j] = bb[tid + 256 * j];
        for (int d = 0; d < DMODEL; d++) {
            const float td = st[d];
            const float* wr = W + (size_t)d * DMODEL;
#pragma unroll
            for (int j = 0; j < 4; j++) acc[j] += td * wr[tid + 256 * j];
        }

        const int loc = row & 63;
        const int tile = row >> 6;
        if (mat == 0) {
#pragma unroll
            for (int j = 0; j < 4; j++)
                g_q[((size_t)b * S_LEN + row) * DMODEL + tid + 256 * j] = acc[j];
        } else if (mat == 1) {
            // K single fp16 patch
#pragma unroll
            for (int j = 0; j < 4; j++) {
                const int col = tid + 256 * j;
                const int h = col >> 6;
                const int c = col & 63;
                const int bh = b * 16 + h;
                const int slot = ((loc >> 3) * 4 + (c >> 4)) * 32 + (loc & 7) * 4 + ((c & 7) >> 1);
                const int word = (c >> 3) & 1;
                const int half = c & 1;
                __half* p = (__half*)(g_kfrag + ((size_t)bh * NKTILES + tile) * 1024 + slot);
                p[word * 2 + half] = __float2half_rn(acc[j]);
            }
        } else {
            // V hi/lo patch
#pragma unroll
            for (int j = 0; j < 4; j++) {
                const int col = tid + 256 * j;
                const int h = col >> 6;
                const int c = col & 63;
                const int bh = b * 16 + h;
                __half hi, lo;
                split2h(acc[j], hi, lo);
                const int slot = ((c >> 3) * 4 + (loc >> 4)) * 32 + (c & 7) * 4 + ((loc & 7) >> 1);
                const int word = (loc >> 3) & 1;
                const int half = loc & 1;
                __half* p = (__half*)(g_vfrag + ((size_t)bh * NKTILES + tile) * 1024 + slot);
                p[word * 2 + half]       = hi;
                p[(word + 2) * 2 + half] = lo;
            }
        }
        return;
    }

    uint4* sA = dyn;
    uint4* sB = dyn + 1024;

    const int tid    = threadIdx.x;
    const int lane   = tid & 31;
    const int wid    = tid >> 5;
    const int nb     = blockIdx.x % 24;
    const int mb     = blockIdx.x / 24;
    const int warp_m = (wid >> 2);
    const int warp_n = (wid & 3);

    const uint4* Ab = g_atok_frag + (size_t)mb * KIT * 512;
    const uint4* Bb = g_wqkv_frag + (size_t)nb * KIT * 1024;

    float acc[4][4][4];
#pragma unroll
    for (int mi = 0; mi < 4; mi++)
#pragma unroll
        for (int ni = 0; ni < 4; ni++)
#pragma unroll
            for (int r = 0; r < 4; r++) acc[mi][ni][r] = 0.f;

#pragma unroll
    for (int i = 0; i < 2; i++) cp_async16(&sA[tid + i * 256], Ab + tid + i * 256);
#pragma unroll
    for (int i = 0; i < 4; i++) cp_async16(&sB[tid + i * 256], Bb + tid + i * 256);
    cp_commit();

    for (int it = 0; it < KIT; it++) {
        const int buf = it & 1;
        if (it + 1 < KIT) {
            const int nbuf = (it + 1) & 1;
            const uint4* na  = Ab + (size_t)(it + 1) * 512;
            const uint4* nb4 = Bb + (size_t)(it + 1) * 1024;
#pragma unroll
            for (int i = 0; i < 2; i++)
                cp_async16(&sA[nbuf * 512 + tid + i * 256], na + tid + i * 256);
#pragma unroll
            for (int i = 0; i < 4; i++)
                cp_async16(&sB[nbuf * 1024 + tid + i * 256], nb4 + tid + i * 256);
            cp_commit();
            cp_wait<1>();
        } else {
            cp_wait<0>();
        }
        __syncthreads();

        const uint4* bA = sA + buf * 512;
        const uint4* bB = sB + buf * 1024;

#pragma unroll
        for (int ks = 0; ks < 2; ks++) {
            uint4 ah[4], bbv[4];
#pragma unroll
            for (int mi = 0; mi < 4; mi++)
                ah[mi] = bA[(ks * 8 + warp_m * 4 + mi) * 32 + lane];
#pragma unroll
            for (int ni = 0; ni < 4; ni++)
                bbv[ni] = bB[(ks * 16 + warp_n * 4 + ni) * 32 + lane];
#pragma unroll
            for (int mi = 0; mi < 4; mi++) {
                const uint32_t* ap = (const uint32_t*)&ah[mi];
#pragma unroll
                for (int ni = 0; ni < 4; ni++) {
                    uint32_t bfr[2] = {bbv[ni].x, bbv[ni].y};
                    uint32_t bfl[2] = {bbv[ni].z, bbv[ni].w};
                    mma_f16(acc[mi][ni], ap, bfr);
                    mma_f16(acc[mi][ni], ap, bfl);
                }
            }
        }
        __syncthreads();
    }

    const int pos = *seqc;
    const int bm  = mb * 128;
    const int bn  = nb * 128;

#pragma unroll
    for (int mi = 0; mi < 4; mi++) {
        const int row = bm + warp_m * 64 + mi * 16 + (lane >> 2);
        const int b   = row >> 11;
        const int s   = row & 2047;
        const int tile = s >> 6;
        const int loc  = s & 63;
#pragma unroll
        for (int ni = 0; ni < 4; ni++) {
            const int col = bn + warp_n * 32 + ni * 8 + (lane & 3) * 2;
            const float2 bv2 = *(const float2*)&bias[col];
            const float x0 = acc[mi][ni][0] + bv2.x;
            const float x1 = acc[mi][ni][1] + bv2.y;
            const float x2 = acc[mi][ni][2] + bv2.x;
            const float x3 = acc[mi][ni][3] + bv2.y;

            if (nb < 8) {
                if (!in_ns(s, pos)) {
                    float2 o = {x0, x1};
                    *(float2*)&g_q[(size_t)row * DMODEL + col] = o;
                }
                if (!in_ns(s + 8, pos)) {
                    float2 o = {x2, x3};
                    *(float2*)&g_q[(size_t)(row + 8) * DMODEL + col] = o;
                }
            } else if (nb < 16) {
                // K frags: single fp16 (uint2 slots)
                const int kc = col & 63;
                const int h  = (col >> 6) & 15;
                uint32_t* kb32 = (uint32_t*)(g_kfrag +
                    ((size_t)(b * 16 + h) * NKTILES + tile) * 1024);
                const uint32_t H0 = pack2h(x0, x1);
                const uint32_t H8 = pack2h(x2, x3);
                const int word  = (kc >> 3) & 1;
                const int slot0 = ((loc >> 3) * 4 + (kc >> 4)) * 32 + (loc & 7) * 4 + ((kc & 7) >> 1);
                if (!in_ns(s, pos))     kb32[slot0 * 2 + word] = H0;
                if (!in_ns(s + 8, pos)) kb32[(slot0 + 128) * 2 + word] = H8;
            } else {
                // V frags hi/lo with shfl transpose
                const int vc = col & 63;
                const int h  = (col >> 6) & 15;
                uint32_t* vb32 = (uint32_t*)(g_vfrag +
                    ((size_t)(b * 16 + h) * NKTILES + tile) * 1024);
                __half2 H0h = __floats2half2_rn(x0, x1);
                __half2 H8h = __floats2half2_rn(x2, x3);
                const uint32_t H0 = *(const uint32_t*)&H0h;
                const uint32_t H8 = *(const uint32_t*)&H8h;
                const uint32_t L0 = pack2h(x0 - __low2float(H0h), x1 - __high2float(H0h));
                const uint32_t L8 = pack2h(x2 - __low2float(H8h), x3 - __high2float(H8h));
                const uint32_t pH0 = __shfl_xor_sync(0xffffffffu, H0, 4);
                const uint32_t pH8 = __shfl_xor_sync(0xffffffffu, H8, 4);
                const uint32_t pL0 = __shfl_xor_sync(0xffffffffu, L0, 4);
                const uint32_t pL8 = __shfl_xor_sync(0xffffffffu, L8, 4);
                if (((lane >> 2) & 1) == 0) {
#pragma unroll
                    for (int pp = 0; pp < 2; pp++) {
                        const int kl = loc + pp * 8;
                        const int kg = s + pp * 8;
                        const uint32_t Ah = pp ? H8 : H0;
                        const uint32_t Bh = pp ? pH8 : pH0;
                        const uint32_t Al = pp ? L8 : L0;
                        const uint32_t Bl = pp ? pL8 : pL0;
                        const bool ok0 = !in_ns(kg, pos);
                        const bool ok1 = !in_ns(kg + 1, pos);
                        const int word = (kl >> 3) & 1;
#pragma unroll
                        for (int dd = 0; dd < 2; dd++) {
                            const int d = vc + dd;
                            const int slot = ((d >> 3) * 4 + (kl >> 4)) * 32 + (d & 7) * 4 + ((kl & 7) >> 1);
                            const uint32_t wh = dd ? __byte_perm(Ah, Bh, 0x7632)
                                                   : __byte_perm(Ah, Bh, 0x5410);
                            const uint32_t wl = dd ? __byte_perm(Al, Bl, 0x7632)
                                                   : __byte_perm(Al, Bl, 0x5410);
                            uint32_t* p = vb32 + slot * 4 + word;
                            if (ok0 && ok1) {
                                p[0] = wh; p[2] = wl;
                            } else {
                                unsigned short* ps = (unsigned short*)p;
                                if (ok0) { ps[0] = (unsigned short)(wh & 0xffff);
                                           ps[4] = (unsigned short)(wl & 0xffff); }
                                if (ok1) { ps[1] = (unsigned short)(wh >> 16);
                                           ps[5] = (unsigned short)(wl >> 16); }
                            }
                        }
                    }
                }
            }
        }
    }
}

// ---------------------------------------------------------------------------
// Output projection frag GEMM (unchanged from R10)
// ---------------------------------------------------------------------------
__global__ void __launch_bounds__(256) gemm_out_kernel(
    const float* __restrict__ bias, float* __restrict__ C)
{
    extern __shared__ uint4 dyn[];
    uint4* sA = dyn;
    uint4* sB = dyn + 1024;

    const int tid    = threadIdx.x;
    const int lane   = tid & 31;
    const int wid    = tid >> 5;
    const int nb     = blockIdx.x;
    const int mb     = blockIdx.y;
    const int warp_m = (wid >> 2);
    const int warp_n = (wid & 3);

    const uint4* Ab = g_actx_frag + (size_t)mb * KIT * 512;
    const uint4* Bb = g_wout_frag + (size_t)nb * KIT * 1024;

    float acc[4][4][4];
#pragma unroll
    for (int mi = 0; mi < 4; mi++)
#pragma unroll
        for (int ni = 0; ni < 4; ni++)
#pragma unroll
            for (int r = 0; r < 4; r++) acc[mi][ni][r] = 0.f;

#pragma unroll
    for (int i = 0; i < 2; i++) cp_async16(&sA[tid + i * 256], Ab + tid + i * 256);
#pragma unroll
    for (int i = 0; i < 4; i++) cp_async16(&sB[tid + i * 256], Bb + tid + i * 256);
    cp_commit();

    for (int it = 0; it < KIT; it++) {
        const int buf = it & 1;
        if (it + 1 < KIT) {
            const int nbuf = (it + 1) & 1;
            const uint4* na  = Ab + (size_t)(it + 1) * 512;
            const uint4* nb4 = Bb + (size_t)(it + 1) * 1024;
#pragma unroll
            for (int i = 0; i < 2; i++)
                cp_async16(&sA[nbuf * 512 + tid + i * 256], na + tid + i * 256);
#pragma unroll
            for (int i = 0; i < 4; i++)
                cp_async16(&sB[nbuf * 1024 + tid + i * 256], nb4 + tid + i * 256);
            cp_commit();
            cp_wait<1>();
        } else {
            cp_wait<0>();
        }
        __syncthreads();

        const uint4* bA = sA + buf * 512;
        const uint4* bB = sB + buf * 1024;

#pragma unroll
        for (int ks = 0; ks < 2; ks++) {
            uint4 ah[4], bbv[4];
#pragma unroll
            for (int mi = 0; mi < 4; mi++)
                ah[mi] = bA[(ks * 8 + warp_m * 4 + mi) * 32 + lane];
#pragma unroll
            for (int ni = 0; ni < 4; ni++)
                bbv[ni] = bB[(ks * 16 + warp_n * 4 + ni) * 32 + lane];
#pragma unroll
            for (int mi = 0; mi < 4; mi++) {
                const uint32_t* ap = (const uint32_t*)&ah[mi];
#pragma unroll
                for (int ni = 0; ni < 4; ni++) {
                    uint32_t bfr[2] = {bbv[ni].x, bbv[ni].y};
                    uint32_t bfl[2] = {bbv[ni].z, bbv[ni].w};
                    mma_f16(acc[mi][ni], ap, bfr);
                    mma_f16(acc[mi][ni], ap, bfl);
                }
            }
        }
        __syncthreads();
    }

    const int bm = mb * 128;
    const int bn = nb * 128;
#pragma unroll
    for (int mi = 0; mi < 4; mi++) {
        const int row = bm + warp_m * 64 + mi * 16 + (lane >> 2);
#pragma unroll
        for (int ni = 0; ni < 4; ni++) {
            const int col = bn + warp_n * 32 + ni * 8 + (lane & 3) * 2;
            const float2 bv2 = *(const float2*)&bias[col];
            float2 o0, o1;
            o0.x = acc[mi][ni][0] + bv2.x;  o0.y = acc[mi][ni][1] + bv2.y;
            o1.x = acc[mi][ni][2] + bv2.x;  o1.y = acc[mi][ni][3] + bv2.y;
            *(float2*)&C[(size_t)row * DMODEL + col]       = o0;
            *(float2*)&C[(size_t)(row + 8) * DMODEL + col] = o1;
        }
    }
}

// ---------------------------------------------------------------------------
// Tensor-core flash attention (R10 smem structure; K single fp16, V hi/lo)
// smem: sK [2][512]u4 (16KB) + sV [2][1024]u4 (32KB) + mask 512B = 49664B
// ---------------------------------------------------------------------------
__global__ void __launch_bounds__(256, 2) attn_tc_kernel(
    const unsigned int* __restrict__ mask)
{
    extern __shared__ uint4 dyn[];
    uint4*    sK    = dyn;                       // 2 x 512 uint4 (K as uint2 pairs)
    uint4*    sV    = dyn + 1024;                // 2 x 1024 uint4
    uint32_t* sMask = (uint32_t*)(dyn + 3072);   // 2 x 64 words

    const int tid  = threadIdx.x;
    const int w    = tid >> 5;
    const int lane = tid & 31;
    const int bxr  = (S_LEN / 128 - 1) - blockIdx.x;
    const int bh   = blockIdx.y;
    const int b    = bh >> 4;
    const int h    = bh & 15;
    const int r0   = bxr * 128;

    const float* qb = g_q + ((size_t)b * S_LEN) * DMODEL + h * HDIM;
    const unsigned int* mb = mask + b * S_LEN;
    const uint4* kfb = (const uint4*)(g_kfrag + ((size_t)bh * NKTILES << 10));
    const uint4* vfb = g_vfrag + ((size_t)bh * NKTILES << 10);

    const int ntiles = (r0 + 128) >> 6;

    // Q fragments, 1/8 scale folded with log2(e) for exp2 softmax
    const float QS = 0.125f * 1.44269504f;
    uint32_t qh[4][4];
    {
        const int rlo = r0 + w * 16 + (lane >> 2);
        const float* q0 = qb + (size_t)rlo * DMODEL;
        const float* q1 = qb + (size_t)(rlo + 8) * DMODEL;
#pragma unroll
        for (int ks = 0; ks < 4; ks++) {
            const int c = ks * 16 + (lane & 3) * 2;
            float2 x0 = *(const float2*)&q0[c];
            float2 x1 = *(const float2*)&q1[c];
            float2 x2 = *(const float2*)&q0[c + 8];
            float2 x3 = *(const float2*)&q1[c + 8];
            qh[ks][0] = pack2h(x0.x * QS, x0.y * QS);
            qh[ks][1] = pack2h(x1.x * QS, x1.y * QS);
            qh[ks][2] = pack2h(x2.x * QS, x2.y * QS);
            qh[ks][3] = pack2h(x3.x * QS, x3.y * QS);
        }
    }

    float m_i[2] = {-1e30f, -1e30f};
    float l_i[2] = {0.f, 0.f};
    float o_acc[8][4];
#pragma unroll
    for (int dt = 0; dt < 8; dt++)
#pragma unroll
        for (int r = 0; r < 4; r++) o_acc[dt][r] = 0.f;

    const int q0g = r0 + w * 16 + (lane >> 2);

    {
#pragma unroll
        for (int i = 0; i < 2; i++)
            cp_async16(&sK[tid + i * 256], kfb + tid + i * 256);
#pragma unroll
        for (int i = 0; i < 4; i++)
            cp_async16(&sV[tid + i * 256], vfb + tid + i * 256);
        if (tid < 16) cp_async16(&sMask[tid * 4], mb + tid * 4);
        cp_commit();
    }

    for (int t = 0; t < ntiles; t++) {
        const int buf = t & 1;
        if (t + 1 < ntiles) {
            const int nb = (t + 1) & 1;
            const uint4* srcK = kfb + ((size_t)(t + 1) << 9);
            const uint4* srcV = vfb + ((size_t)(t + 1) << 10);
#pragma unroll
            for (int i = 0; i < 2; i++)
                cp_async16(&sK[nb * 512 + tid + i * 256], srcK + tid + i * 256);
#pragma unroll
            for (int i = 0; i < 4; i++)
                cp_async16(&sV[nb * 1024 + tid + i * 256], srcV + tid + i * 256);
            if (tid < 16) cp_async16(&sMask[nb * 64 + tid * 4], mb + (t + 1) * 64 + tid * 4);
            cp_commit();
            cp_wait<1>();
        } else {
            cp_wait<0>();
        }
        __syncthreads();

        const int k0 = t << 6;
        const uint2* bK = (const uint2*)(sK + buf * 512);
        const uint4* bV = sV + buf * 1024;
        const uint32_t* bM = sMask + buf * 64;

        float s[8][4];
#pragma unroll
        for (int nt = 0; nt < 8; nt++)
#pragma unroll
            for (int r = 0; r < 4; r++) s[nt][r] = 0.f;

#pragma unroll
        for (int ks = 0; ks < 4; ks++) {
#pragma unroll
            for (int nt = 0; nt < 8; nt++) {
                const uint2 v = bK[(nt * 4 + ks) * 32 + lane];
                uint32_t bfr[2] = {v.x, v.y};
                mma_f16(s[nt], qh[ks], bfr);
            }
        }

#pragma unroll
        for (int row = 0; row < 2; row++) {
            const int qg = q0g + row * 8;
            float mx = -1e30f;
#pragma unroll
            for (int nt = 0; nt < 8; nt++)
#pragma unroll
                for (int c = 0; c < 2; c++) {
                    const int idx = row * 2 + c;
                    const int kl  = nt * 8 + (lane & 3) * 2 + c;
                    const bool ok = (bM[kl] != 0u) && (k0 + kl <= qg);
                    s[nt][idx] = ok ? s[nt][idx] : -1e9f;
                    mx = fmaxf(mx, s[nt][idx]);
                }
            mx = fmaxf(mx, __shfl_xor_sync(0xffffffffu, mx, 1));
            mx = fmaxf(mx, __shfl_xor_sync(0xffffffffu, mx, 2));
            const float mnew = fmaxf(m_i[row], mx);
            const float corr = exp2f(m_i[row] - mnew);
            float sum = 0.f;
#pragma unroll
            for (int nt = 0; nt < 8; nt++)
#pragma unroll
                for (int c = 0; c < 2; c++) {
                    const int idx = row * 2 + c;
                    const float p = exp2f(s[nt][idx] - mnew);
                    s[nt][idx] = p;
                    sum += p;
                }
            sum += __shfl_xor_sync(0xffffffffu, sum, 1);
            sum += __shfl_xor_sync(0xffffffffu, sum, 2);
            l_i[row] = l_i[row] * corr + sum;
            m_i[row] = mnew;
#pragma unroll
            for (int dt = 0; dt < 8; dt++) {
                o_acc[dt][row * 2 + 0] *= corr;
                o_acc[dt][row * 2 + 1] *= corr;
            }
        }

#pragma unroll
        for (int ks2 = 0; ks2 < 4; ks2++) {
            uint32_t pah[4];
            pah[0] = pack2h(s[ks2*2][0],   s[ks2*2][1]);
            pah[1] = pack2h(s[ks2*2][2],   s[ks2*2][3]);
            pah[2] = pack2h(s[ks2*2+1][0], s[ks2*2+1][1]);
            pah[3] = pack2h(s[ks2*2+1][2], s[ks2*2+1][3]);
#pragma unroll
            for (int dt = 0; dt < 8; dt++) {
                const uint4 v = bV[(dt * 4 + ks2) * 32 + lane];
                uint32_t bfr[2] = {v.x, v.y};
                uint32_t bfl[2] = {v.z, v.w};
                mma_f16(o_acc[dt], pah, bfr);
                mma_f16(o_acc[dt], pah, bfl);
            }
        }
        __syncthreads();
    }

    // epilogue: emit ctx A-fragments (fp16)
    const float inv0 = 1.f / l_i[0];
    const float inv1 = 1.f / l_i[1];
    uint4* dst = g_actx_frag + ((size_t)(b * 16 + (r0 >> 7)) * KIT) * 512;
#pragma unroll
    for (int f = 0; f < 4; f++) {
        const int it  = h * 2 + (f >> 1);
        const int ks  = f & 1;
        const int dt0 = f * 2, dt1 = f * 2 + 1;
        uint4 u;
        u.x = pack2h(o_acc[dt0][0] * inv0, o_acc[dt0][1] * inv0);
        u.y = pack2h(o_acc[dt0][2] * inv1, o_acc[dt0][3] * inv1);
        u.z = pack2h(o_acc[dt1][0] * inv0, o_acc[dt1][1] * inv0);
        u.w = pack2h(o_acc[dt1][2] * inv1, o_acc[dt1][3] * inv1);
        dst[(size_t)it * 512 + (ks * 8 + w) * 32 + lane] = u;
    }
}

// ---------------------------------------------------------------------------
extern "C" void kernel_launch(void* const* d_in, const int* in_sizes, int n_in,
                              void* d_out, int out_size)
{
    const float*        tokens = (const float*)d_in[0];
    const unsigned int* mask   = (const unsigned int*)d_in[1];
    const int*          seqc   = (const int*)d_in[2];
    const float*        W_qkv  = (const float*)d_in[3];
    const float*        b_qkv  = (const float*)d_in[4];
    const float*        Wq     = (const float*)d_in[5];
    const float*        bq     = (const float*)d_in[6];
    const float*        Wk     = (const float*)d_in[7];
    const float*        bk     = (const float*)d_in[8];
    const float*        Wv     = (const float*)d_in[9];
    const float*        bv     = (const float*)d_in[10];
    const float*        W_out  = (const float*)d_in[11];
    const float*        b_out  = (const float*)d_in[12];
    float*              out    = (float*)d_out;

    cudaFuncSetAttribute(gemm_qkv_kernel,
                         cudaFuncAttributeMaxDynamicSharedMemorySize, 49152);
    cudaFuncSetAttribute(gemm_out_kernel,
                         cudaFuncAttributeMaxDynamicSharedMemorySize, 49152);
    cudaFuncSetAttribute(attn_tc_kernel,
                         cudaFuncAttributeMaxDynamicSharedMemorySize, 49664);

    // 1) all operand presplits
    presplit_all_kernel<<<2048, 256>>>(tokens, W_qkv, W_out);

    // 2) QKV projection + fused K/V frag emission + fused ns blocks
    gemm_qkv_kernel<<<816, 256, 49152>>>(b_qkv, tokens, seqc,
                                         Wq, bq, Wk, bk, Wv, bv);

    // 3) attention (smem-staged, K single fp16, emits ctx A-fragments)
    dim3 g2(S_LEN / 128, BATCH * NHEADS);
    attn_tc_kernel<<<g2, 256, 49664>>>(mask);

    // 4) output projection -> d_out
    dim3 g3(DMODEL / 128, MBLK);
    gemm_out_kernel<<<g3, 256, 49152>>>(b_out, out);
}

// round 13
// speedup vs baseline: 1.0604x; 1.0604x over previous
#include <cuda_runtime.h>
#include <cuda_fp16.h>
#include <cstdint>

#define S_LEN   2048
#define DMODEL  1024
#define BATCH   2
#define NHEADS  16
#define HDIM    64
#define QKV_LD  3072
#define NKTILES (S_LEN / 64)
#define MROWS   (BATCH * S_LEN)   // 4096
#define MBLK    (MROWS / 128)     // 32
#define KIT     (DMODEL / 32)     // 32

__device__ float g_q[(size_t)MROWS * DMODEL];           // dense Q fp32
__device__ uint2 g_kfrag[(size_t)BATCH * NHEADS * NKTILES * 1024];  // K single fp16
__device__ uint2 g_vfrag[(size_t)BATCH * NHEADS * NKTILES * 1024];  // V single fp16
__device__ uint4 g_wqkv_frag[(size_t)(QKV_LD / 128) * KIT * 1024];
__device__ uint4 g_wout_frag[(size_t)(DMODEL / 128) * KIT * 1024];
__device__ uint4 g_atok_frag[(size_t)MBLK * KIT * 512];
__device__ uint4 g_actx_frag[(size_t)MBLK * KIT * 512];

// ---------------------------------------------------------------------------
__device__ __forceinline__ void mma_f16(float* d, const uint32_t* a, const uint32_t* b) {
    asm volatile(
        "mma.sync.aligned.m16n8k16.row.col.f32.f16.f16.f32 "
        "{%0,%1,%2,%3}, {%4,%5,%6,%7}, {%8,%9}, {%0,%1,%2,%3};\n"
        : "+f"(d[0]), "+f"(d[1]), "+f"(d[2]), "+f"(d[3])
        : "r"(a[0]), "r"(a[1]), "r"(a[2]), "r"(a[3]), "r"(b[0]), "r"(b[1]));
}

__device__ __forceinline__ void split2h(float x, __half& hi, __half& lo) {
    hi = __float2half_rn(x);
    lo = __float2half_rn(x - __half2float(hi));
}

__device__ __forceinline__ uint32_t pack2h(float x, float y) {
    __half2 h = __floats2half2_rn(x, y);
    return *(uint32_t*)&h;
}

__device__ __forceinline__ void cp_async16(void* smem_ptr, const void* gptr) {
    uint32_t sa = (uint32_t)__cvta_generic_to_shared(smem_ptr);
    asm volatile("cp.async.cg.shared.global [%0], [%1], 16;\n" :: "r"(sa), "l"(gptr));
}
__device__ __forceinline__ void cp_commit() {
    asm volatile("cp.async.commit_group;\n");
}
template <int N>
__device__ __forceinline__ void cp_wait() {
    asm volatile("cp.async.wait_group %0;\n" :: "n"(N));
}

__device__ __forceinline__ bool in_ns(int s, int pos) {
    return (unsigned)(s - pos) < 8u;
}

// ---------------------------------------------------------------------------
// Combined presplit: [0,768) W_qkv B-frags, [768,1024) W_out B-frags,
// [1024,2048) tokens A-frags.
// ---------------------------------------------------------------------------
__global__ void __launch_bounds__(256) presplit_all_kernel(
    const float* __restrict__ tokens, const float* __restrict__ W_qkv,
    const float* __restrict__ W_out)
{
    const int bid = blockIdx.x;
    if (bid < 1024) {
        const float* W;
        uint4* out;
        int N, j;
        if (bid < 768) { W = W_qkv; out = g_wqkv_frag; N = QKV_LD; j = bid; }
        else           { W = W_out; out = g_wout_frag; N = DMODEL; j = bid - 768; }
        const int it = j & 31;
        const int nb = j >> 5;
        uint4* chunk = out + ((size_t)nb * KIT + it) * 1024;
#pragma unroll
        for (int i = 0; i < 4; i++) {
            const int s    = threadIdx.x + i * 256;
            const int lane = s & 31;
            const int n8   = (s >> 5) & 15;
            const int ks   = s >> 9;
            const int n = nb * 128 + n8 * 8 + (lane >> 2);
            const int k = it * 32 + ks * 16 + (lane & 3) * 2;
            const float b0 = W[(size_t)k * N + n];
            const float b1 = W[(size_t)(k + 1) * N + n];
            const float b2 = W[(size_t)(k + 8) * N + n];
            const float b3 = W[(size_t)(k + 9) * N + n];
            __half h0, l0, h1, l1, h2, l2, h3, l3;
            split2h(b0, h0, l0); split2h(b1, h1, l1);
            split2h(b2, h2, l2); split2h(b3, h3, l3);
            __half2 whi0(h0, h1), whi1(h2, h3), wlo0(l0, l1), wlo1(l2, l3);
            chunk[s] = make_uint4(*(uint32_t*)&whi0, *(uint32_t*)&whi1,
                                  *(uint32_t*)&wlo0, *(uint32_t*)&wlo1);
        }
    } else {
        const int j  = bid - 1024;
        const int it = j & 31;
        const int mb = j >> 5;
        uint4* chunk = g_atok_frag + ((size_t)mb * KIT + it) * 512;
#pragma unroll
        for (int i = 0; i < 2; i++) {
            const int s    = threadIdx.x + i * 256;
            const int lane = s & 31;
            const int mt   = (s >> 5) & 7;
            const int ks   = s >> 8;
            const int m = mb * 128 + mt * 16 + (lane >> 2);
            const int k = it * 32 + ks * 16 + (lane & 3) * 2;
            const float2 r0 = *(const float2*)&tokens[(size_t)m * DMODEL + k];
            const float2 r1 = *(const float2*)&tokens[(size_t)(m + 8) * DMODEL + k];
            const float2 r2 = *(const float2*)&tokens[(size_t)m * DMODEL + k + 8];
            const float2 r3 = *(const float2*)&tokens[(size_t)(m + 8) * DMODEL + k + 8];
            chunk[s] = make_uint4(pack2h(r0.x, r0.y), pack2h(r1.x, r1.y),
                                  pack2h(r2.x, r2.y), pack2h(r3.x, r3.y));
        }
    }
}

// ---------------------------------------------------------------------------
// QKV frag GEMM + fused frag emission (K and V single fp16) + ns blocks.
// ---------------------------------------------------------------------------
__global__ void __launch_bounds__(256) gemm_qkv_kernel(
    const float* __restrict__ bias, const float* __restrict__ tokens,
    const int* __restrict__ seqc,
    const float* __restrict__ Wq, const float* __restrict__ bq,
    const float* __restrict__ Wk, const float* __restrict__ bk,
    const float* __restrict__ Wv, const float* __restrict__ bv)
{
    extern __shared__ uint4 dyn[];

    if (blockIdx.x >= 768) {
        float* st = (float*)dyn;
        const int bid2 = blockIdx.x - 768;
        const int mat = bid2 >> 4;
        const int b   = (bid2 >> 3) & 1;
        const int n   = bid2 & 7;
        const int pos = *seqc;
        const int row = pos + n;
        if (pos < 0 || row < 0 || row >= S_LEN) return;

        const float* W; const float* bb;
        if (mat == 0)      { W = Wq; bb = bq; }
        else if (mat == 1) { W = Wk; bb = bk; }
        else               { W = Wv; bb = bv; }
        W  += (size_t)n * DMODEL * DMODEL;
        bb += n * DMODEL;

        const float* trow = tokens + ((size_t)b * S_LEN + row) * DMODEL;
        const int tid = threadIdx.x;
        *(float4*)&st[tid * 4] = *(const float4*)&trow[tid * 4];
        __syncthreads();

        float acc[4];
#pragma unroll
        for (int j = 0; j < 4; j++) acc[j] = bb[tid + 256 * j];
        for (int d = 0; d < DMODEL; d++) {
            const float td = st[d];
            const float* wr = W + (size_t)d * DMODEL;
#pragma unroll
            for (int j = 0; j < 4; j++) acc[j] += td * wr[tid + 256 * j];
        }

        const int loc = row & 63;
        const int tile = row >> 6;
        if (mat == 0) {
#pragma unroll
            for (int j = 0; j < 4; j++)
                g_q[((size_t)b * S_LEN + row) * DMODEL + tid + 256 * j] = acc[j];
        } else if (mat == 1) {
#pragma unroll
            for (int j = 0; j < 4; j++) {
                const int col = tid + 256 * j;
                const int h = col >> 6;
                const int c = col & 63;
                const int bh = b * 16 + h;
                const int slot = ((loc >> 3) * 4 + (c >> 4)) * 32 + (loc & 7) * 4 + ((c & 7) >> 1);
                const int word = (c >> 3) & 1;
                const int half = c & 1;
                __half* p = (__half*)(g_kfrag + ((size_t)bh * NKTILES + tile) * 1024 + slot);
                p[word * 2 + half] = __float2half_rn(acc[j]);
            }
        } else {
#pragma unroll
            for (int j = 0; j < 4; j++) {
                const int col = tid + 256 * j;
                const int h = col >> 6;
                const int c = col & 63;
                const int bh = b * 16 + h;
                const int slot = ((c >> 3) * 4 + (loc >> 4)) * 32 + (c & 7) * 4 + ((loc & 7) >> 1);
                const int word = (loc >> 3) & 1;
                const int half = loc & 1;
                __half* p = (__half*)(g_vfrag + ((size_t)bh * NKTILES + tile) * 1024 + slot);
                p[word * 2 + half] = __float2half_rn(acc[j]);
            }
        }
        return;
    }

    uint4* sA = dyn;
    uint4* sB = dyn + 1024;

    const int tid    = threadIdx.x;
    const int lane   = tid & 31;
    const int wid    = tid >> 5;
    const int nb     = blockIdx.x % 24;
    const int mb     = blockIdx.x / 24;
    const int warp_m = (wid >> 2);
    const int warp_n = (wid & 3);

    const uint4* Ab = g_atok_frag + (size_t)mb * KIT * 512;
    const uint4* Bb = g_wqkv_frag + (size_t)nb * KIT * 1024;

    float acc[4][4][4];
#pragma unroll
    for (int mi = 0; mi < 4; mi++)
#pragma unroll
        for (int ni = 0; ni < 4; ni++)
#pragma unroll
            for (int r = 0; r < 4; r++) acc[mi][ni][r] = 0.f;

#pragma unroll
    for (int i = 0; i < 2; i++) cp_async16(&sA[tid + i * 256], Ab + tid + i * 256);
#pragma unroll
    for (int i = 0; i < 4; i++) cp_async16(&sB[tid + i * 256], Bb + tid + i * 256);
    cp_commit();

    for (int it = 0; it < KIT; it++) {
        const int buf = it & 1;
        if (it + 1 < KIT) {
            const int nbuf = (it + 1) & 1;
            const uint4* na  = Ab + (size_t)(it + 1) * 512;
            const uint4* nb4 = Bb + (size_t)(it + 1) * 1024;
#pragma unroll
            for (int i = 0; i < 2; i++)
                cp_async16(&sA[nbuf * 512 + tid + i * 256], na + tid + i * 256);
#pragma unroll
            for (int i = 0; i < 4; i++)
                cp_async16(&sB[nbuf * 1024 + tid + i * 256], nb4 + tid + i * 256);
            cp_commit();
            cp_wait<1>();
        } else {
            cp_wait<0>();
        }
        __syncthreads();

        const uint4* bA = sA + buf * 512;
        const uint4* bB = sB + buf * 1024;

#pragma unroll
        for (int ks = 0; ks < 2; ks++) {
            uint4 ah[4], bbv[4];
#pragma unroll
            for (int mi = 0; mi < 4; mi++)
                ah[mi] = bA[(ks * 8 + warp_m * 4 + mi) * 32 + lane];
#pragma unroll
            for (int ni = 0; ni < 4; ni++)
                bbv[ni] = bB[(ks * 16 + warp_n * 4 + ni) * 32 + lane];
#pragma unroll
            for (int mi = 0; mi < 4; mi++) {
                const uint32_t* ap = (const uint32_t*)&ah[mi];
#pragma unroll
                for (int ni = 0; ni < 4; ni++) {
                    uint32_t bfr[2] = {bbv[ni].x, bbv[ni].y};
                    uint32_t bfl[2] = {bbv[ni].z, bbv[ni].w};
                    mma_f16(acc[mi][ni], ap, bfr);
                    mma_f16(acc[mi][ni], ap, bfl);
                }
            }
        }
        __syncthreads();
    }

    const int pos = *seqc;
    const int bm  = mb * 128;
    const int bn  = nb * 128;

#pragma unroll
    for (int mi = 0; mi < 4; mi++) {
        const int row = bm + warp_m * 64 + mi * 16 + (lane >> 2);
        const int b   = row >> 11;
        const int s   = row & 2047;
        const int tile = s >> 6;
        const int loc  = s & 63;
#pragma unroll
        for (int ni = 0; ni < 4; ni++) {
            const int col = bn + warp_n * 32 + ni * 8 + (lane & 3) * 2;
            const float2 bv2 = *(const float2*)&bias[col];
            const float x0 = acc[mi][ni][0] + bv2.x;
            const float x1 = acc[mi][ni][1] + bv2.y;
            const float x2 = acc[mi][ni][2] + bv2.x;
            const float x3 = acc[mi][ni][3] + bv2.y;

            if (nb < 8) {
                if (!in_ns(s, pos)) {
                    float2 o = {x0, x1};
                    *(float2*)&g_q[(size_t)row * DMODEL + col] = o;
                }
                if (!in_ns(s + 8, pos)) {
                    float2 o = {x2, x3};
                    *(float2*)&g_q[(size_t)(row + 8) * DMODEL + col] = o;
                }
            } else if (nb < 16) {
                // K frags: single fp16 (uint2 slots)
                const int kc = col & 63;
                const int h  = (col >> 6) & 15;
                uint32_t* kb32 = (uint32_t*)(g_kfrag +
                    ((size_t)(b * 16 + h) * NKTILES + tile) * 1024);
                const uint32_t H0 = pack2h(x0, x1);
                const uint32_t H8 = pack2h(x2, x3);
                const int word  = (kc >> 3) & 1;
                const int slot0 = ((loc >> 3) * 4 + (kc >> 4)) * 32 + (loc & 7) * 4 + ((kc & 7) >> 1);
                if (!in_ns(s, pos))     kb32[slot0 * 2 + word] = H0;
                if (!in_ns(s + 8, pos)) kb32[(slot0 + 128) * 2 + word] = H8;
            } else {
                // V frags: single fp16 with shfl transpose
                const int vc = col & 63;
                const int h  = (col >> 6) & 15;
                uint32_t* vb32 = (uint32_t*)(g_vfrag +
                    ((size_t)(b * 16 + h) * NKTILES + tile) * 1024);
                const uint32_t H0 = pack2h(x0, x1);
                const uint32_t H8 = pack2h(x2, x3);
                const uint32_t pH0 = __shfl_xor_sync(0xffffffffu, H0, 4);
                const uint32_t pH8 = __shfl_xor_sync(0xffffffffu, H8, 4);
                if (((lane >> 2) & 1) == 0) {
#pragma unroll
                    for (int pp = 0; pp < 2; pp++) {
                        const int kl = loc + pp * 8;
                        const int kg = s + pp * 8;
                        const uint32_t Ah = pp ? H8 : H0;
                        const uint32_t Bh = pp ? pH8 : pH0;
                        const bool ok0 = !in_ns(kg, pos);
                        const bool ok1 = !in_ns(kg + 1, pos);
                        const int word = (kl >> 3) & 1;
#pragma unroll
                        for (int dd = 0; dd < 2; dd++) {
                            const int d = vc + dd;
                            const int slot = ((d >> 3) * 4 + (kl >> 4)) * 32 + (d & 7) * 4 + ((kl & 7) >> 1);
                            const uint32_t wh = dd ? __byte_perm(Ah, Bh, 0x7632)
                                                   : __byte_perm(Ah, Bh, 0x5410);
                            uint32_t* p = vb32 + slot * 2 + word;
                            if (ok0 && ok1) {
                                p[0] = wh;
                            } else {
                                unsigned short* ps = (unsigned short*)p;
                                if (ok0) ps[0] = (unsigned short)(wh & 0xffff);
                                if (ok1) ps[1] = (unsigned short)(wh >> 16);
                            }
                        }
                    }
                }
            }
        }
    }
}

// ---------------------------------------------------------------------------
// Output projection frag GEMM (unchanged)
// ---------------------------------------------------------------------------
__global__ void __launch_bounds__(256) gemm_out_kernel(
    const float* __restrict__ bias, float* __restrict__ C)
{
    extern __shared__ uint4 dyn[];
    uint4* sA = dyn;
    uint4* sB = dyn + 1024;

    const int tid    = threadIdx.x;
    const int lane   = tid & 31;
    const int wid    = tid >> 5;
    const int nb     = blockIdx.x;
    const int mb     = blockIdx.y;
    const int warp_m = (wid >> 2);
    const int warp_n = (wid & 3);

    const uint4* Ab = g_actx_frag + (size_t)mb * KIT * 512;
    const uint4* Bb = g_wout_frag + (size_t)nb * KIT * 1024;

    float acc[4][4][4];
#pragma unroll
    for (int mi = 0; mi < 4; mi++)
#pragma unroll
        for (int ni = 0; ni < 4; ni++)
#pragma unroll
            for (int r = 0; r < 4; r++) acc[mi][ni][r] = 0.f;

#pragma unroll
    for (int i = 0; i < 2; i++) cp_async16(&sA[tid + i * 256], Ab + tid + i * 256);
#pragma unroll
    for (int i = 0; i < 4; i++) cp_async16(&sB[tid + i * 256], Bb + tid + i * 256);
    cp_commit();

    for (int it = 0; it < KIT; it++) {
        const int buf = it & 1;
        if (it + 1 < KIT) {
            const int nbuf = (it + 1) & 1;
            const uint4* na  = Ab + (size_t)(it + 1) * 512;
            const uint4* nb4 = Bb + (size_t)(it + 1) * 1024;
#pragma unroll
            for (int i = 0; i < 2; i++)
                cp_async16(&sA[nbuf * 512 + tid + i * 256], na + tid + i * 256);
#pragma unroll
            for (int i = 0; i < 4; i++)
                cp_async16(&sB[nbuf * 1024 + tid + i * 256], nb4 + tid + i * 256);
            cp_commit();
            cp_wait<1>();
        } else {
            cp_wait<0>();
        }
        __syncthreads();

        const uint4* bA = sA + buf * 512;
        const uint4* bB = sB + buf * 1024;

#pragma unroll
        for (int ks = 0; ks < 2; ks++) {
            uint4 ah[4], bbv[4];
#pragma unroll
            for (int mi = 0; mi < 4; mi++)
                ah[mi] = bA[(ks * 8 + warp_m * 4 + mi) * 32 + lane];
#pragma unroll
            for (int ni = 0; ni < 4; ni++)
                bbv[ni] = bB[(ks * 16 + warp_n * 4 + ni) * 32 + lane];
#pragma unroll
            for (int mi = 0; mi < 4; mi++) {
                const uint32_t* ap = (const uint32_t*)&ah[mi];
#pragma unroll
                for (int ni = 0; ni < 4; ni++) {
                    uint32_t bfr[2] = {bbv[ni].x, bbv[ni].y};
                    uint32_t bfl[2] = {bbv[ni].z, bbv[ni].w};
                    mma_f16(acc[mi][ni], ap, bfr);
                    mma_f16(acc[mi][ni], ap, bfl);
                }
            }
        }
        __syncthreads();
    }

    const int bm = mb * 128;
    const int bn = nb * 128;
#pragma unroll
    for (int mi = 0; mi < 4; mi++) {
        const int row = bm + warp_m * 64 + mi * 16 + (lane >> 2);
#pragma unroll
        for (int ni = 0; ni < 4; ni++) {
            const int col = bn + warp_n * 32 + ni * 8 + (lane & 3) * 2;
            const float2 bv2 = *(const float2*)&bias[col];
            float2 o0, o1;
            o0.x = acc[mi][ni][0] + bv2.x;  o0.y = acc[mi][ni][1] + bv2.y;
            o1.x = acc[mi][ni][2] + bv2.x;  o1.y = acc[mi][ni][3] + bv2.y;
            *(float2*)&C[(size_t)row * DMODEL + col]       = o0;
            *(float2*)&C[(size_t)(row + 8) * DMODEL + col] = o1;
        }
    }
}

// ---------------------------------------------------------------------------
// Tensor-core flash attention: K and V single fp16 in smem.
// smem: sK 2x8KB + sV 2x8KB + mask 512B = 33280B
// ---------------------------------------------------------------------------
__global__ void __launch_bounds__(256, 2) attn_tc_kernel(
    const unsigned int* __restrict__ mask)
{
    extern __shared__ uint4 dyn[];
    uint4*    sK    = dyn;                       // 2 x 512 uint4
    uint4*    sV    = dyn + 1024;                // 2 x 512 uint4
    uint32_t* sMask = (uint32_t*)(dyn + 2048);   // 2 x 64 words

    const int tid  = threadIdx.x;
    const int w    = tid >> 5;
    const int lane = tid & 31;
    const int bxr  = (S_LEN / 128 - 1) - blockIdx.x;
    const int bh   = blockIdx.y;
    const int b    = bh >> 4;
    const int h    = bh & 15;
    const int r0   = bxr * 128;

    const float* qb = g_q + ((size_t)b * S_LEN) * DMODEL + h * HDIM;
    const unsigned int* mb = mask + b * S_LEN;
    const uint4* kfb = (const uint4*)(g_kfrag + ((size_t)bh * NKTILES << 10));
    const uint4* vfb = (const uint4*)(g_vfrag + ((size_t)bh * NKTILES << 10));

    const int ntiles = (r0 + 128) >> 6;

    const float QS = 0.125f * 1.44269504f;
    uint32_t qh[4][4];
    {
        const int rlo = r0 + w * 16 + (lane >> 2);
        const float* q0 = qb + (size_t)rlo * DMODEL;
        const float* q1 = qb + (size_t)(rlo + 8) * DMODEL;
#pragma unroll
        for (int ks = 0; ks < 4; ks++) {
            const int c = ks * 16 + (lane & 3) * 2;
            float2 x0 = *(const float2*)&q0[c];
            float2 x1 = *(const float2*)&q1[c];
            float2 x2 = *(const float2*)&q0[c + 8];
            float2 x3 = *(const float2*)&q1[c + 8];
            qh[ks][0] = pack2h(x0.x * QS, x0.y * QS);
            qh[ks][1] = pack2h(x1.x * QS, x1.y * QS);
            qh[ks][2] = pack2h(x2.x * QS, x2.y * QS);
            qh[ks][3] = pack2h(x3.x * QS, x3.y * QS);
        }
    }

    float m_i[2] = {-1e30f, -1e30f};
    float l_i[2] = {0.f, 0.f};
    float o_acc[8][4];
#pragma unroll
    for (int dt = 0; dt < 8; dt++)
#pragma unroll
        for (int r = 0; r < 4; r++) o_acc[dt][r] = 0.f;

    const int q0g = r0 + w * 16 + (lane >> 2);

    {
#pragma unroll
        for (int i = 0; i < 2; i++) {
            cp_async16(&sK[tid + i * 256], kfb + tid + i * 256);
            cp_async16(&sV[tid + i * 256], vfb + tid + i * 256);
        }
        if (tid < 16) cp_async16(&sMask[tid * 4], mb + tid * 4);
        cp_commit();
    }

    for (int t = 0; t < ntiles; t++) {
        const int buf = t & 1;
        if (t + 1 < ntiles) {
            const int nb = (t + 1) & 1;
            const uint4* srcK = kfb + ((size_t)(t + 1) << 9);
            const uint4* srcV = vfb + ((size_t)(t + 1) << 9);
#pragma unroll
            for (int i = 0; i < 2; i++) {
                cp_async16(&sK[nb * 512 + tid + i * 256], srcK + tid + i * 256);
                cp_async16(&sV[nb * 512 + tid + i * 256], srcV + tid + i * 256);
            }
            if (tid < 16) cp_async16(&sMask[nb * 64 + tid * 4], mb + (t + 1) * 64 + tid * 4);
            cp_commit();
            cp_wait<1>();
        } else {
            cp_wait<0>();
        }
        __syncthreads();

        const int k0 = t << 6;
        const uint2* bK = (const uint2*)(sK + buf * 512);
        const uint2* bV = (const uint2*)(sV + buf * 512);
        const uint32_t* bM = sMask + buf * 64;

        float s[8][4];
#pragma unroll
        for (int nt = 0; nt < 8; nt++)
#pragma unroll
            for (int r = 0; r < 4; r++) s[nt][r] = 0.f;

#pragma unroll
        for (int ks = 0; ks < 4; ks++) {
#pragma unroll
            for (int nt = 0; nt < 8; nt++) {
                const uint2 v = bK[(nt * 4 + ks) * 32 + lane];
                uint32_t bfr[2] = {v.x, v.y};
                mma_f16(s[nt], qh[ks], bfr);
            }
        }

#pragma unroll
        for (int row = 0; row < 2; row++) {
            const int qg = q0g + row * 8;
            float mx = -1e30f;
#pragma unroll
            for (int nt = 0; nt < 8; nt++)
#pragma unroll
                for (int c = 0; c < 2; c++) {
                    const int idx = row * 2 + c;
                    const int kl  = nt * 8 + (lane & 3) * 2 + c;
                    const bool ok = (bM[kl] != 0u) && (k0 + kl <= qg);
                    s[nt][idx] = ok ? s[nt][idx] : -1e9f;
                    mx = fmaxf(mx, s[nt][idx]);
                }
            mx = fmaxf(mx, __shfl_xor_sync(0xffffffffu, mx, 1));
            mx = fmaxf(mx, __shfl_xor_sync(0xffffffffu, mx, 2));
            const float mnew = fmaxf(m_i[row], mx);
            const float corr = exp2f(m_i[row] - mnew);
            float sum = 0.f;
#pragma unroll
            for (int nt = 0; nt < 8; nt++)
#pragma unroll
                for (int c = 0; c < 2; c++) {
                    const int idx = row * 2 + c;
                    const float p = exp2f(s[nt][idx] - mnew);
                    s[nt][idx] = p;
                    sum += p;
                }
            sum += __shfl_xor_sync(0xffffffffu, sum, 1);
            sum += __shfl_xor_sync(0xffffffffu, sum, 2);
            l_i[row] = l_i[row] * corr + sum;
            m_i[row] = mnew;
#pragma unroll
            for (int dt = 0; dt < 8; dt++) {
                o_acc[dt][row * 2 + 0] *= corr;
                o_acc[dt][row * 2 + 1] *= corr;
            }
        }

#pragma unroll
        for (int ks2 = 0; ks2 < 4; ks2++) {
            uint32_t pah[4];
            pah[0] = pack2h(s[ks2*2][0],   s[ks2*2][1]);
            pah[1] = pack2h(s[ks2*2][2],   s[ks2*2][3]);
            pah[2] = pack2h(s[ks2*2+1][0], s[ks2*2+1][1]);
            pah[3] = pack2h(s[ks2*2+1][2], s[ks2*2+1][3]);
#pragma unroll
            for (int dt = 0; dt < 8; dt++) {
                const uint2 v = bV[(dt * 4 + ks2) * 32 + lane];
                uint32_t bfr[2] = {v.x, v.y};
                mma_f16(o_acc[dt], pah, bfr);
            }
        }
        __syncthreads();
    }

    // epilogue: emit ctx A-fragments (fp16)
    const float inv0 = 1.f / l_i[0];
    const float inv1 = 1.f / l_i[1];
    uint4* dst = g_actx_frag + ((size_t)(b * 16 + (r0 >> 7)) * KIT) * 512;
#pragma unroll
    for (int f = 0; f < 4; f++) {
        const int it  = h * 2 + (f >> 1);
        const int ks  = f & 1;
        const int dt0 = f * 2, dt1 = f * 2 + 1;
        uint4 u;
        u.x = pack2h(o_acc[dt0][0] * inv0, o_acc[dt0][1] * inv0);
        u.y = pack2h(o_acc[dt0][2] * inv1, o_acc[dt0][3] * inv1);
        u.z = pack2h(o_acc[dt1][0] * inv0, o_acc[dt1][1] * inv0);
        u.w = pack2h(o_acc[dt1][2] * inv1, o_acc[dt1][3] * inv1);
        dst[(size_t)it * 512 + (ks * 8 + w) * 32 + lane] = u;
    }
}

// ---------------------------------------------------------------------------
extern "C" void kernel_launch(void* const* d_in, const int* in_sizes, int n_in,
                              void* d_out, int out_size)
{
    const float*        tokens = (const float*)d_in[0];
    const unsigned int* mask   = (const unsigned int*)d_in[1];
    const int*          seqc   = (const int*)d_in[2];
    const float*        W_qkv  = (const float*)d_in[3];
    const float*        b_qkv  = (const float*)d_in[4];
    const float*        Wq     = (const float*)d_in[5];
    const float*        bq     = (const float*)d_in[6];
    const float*        Wk     = (const float*)d_in[7];
    const float*        bk     = (const float*)d_in[8];
    const float*        Wv     = (const float*)d_in[9];
    const float*        bv     = (const float*)d_in[10];
    const float*        W_out  = (const float*)d_in[11];
    const float*        b_out  = (const float*)d_in[12];
    float*              out    = (float*)d_out;

    cudaFuncSetAttribute(gemm_qkv_kernel,
                         cudaFuncAttributeMaxDynamicSharedMemorySize, 49152);
    cudaFuncSetAttribute(gemm_out_kernel,
                         cudaFuncAttributeMaxDynamicSharedMemorySize, 49152);
    cudaFuncSetAttribute(attn_tc_kernel,
                         cudaFuncAttributeMaxDynamicSharedMemorySize, 33280);

    // 1) all operand presplits
    presplit_all_kernel<<<2048, 256>>>(tokens, W_qkv, W_out);

    // 2) QKV projection + fused K/V frag emission + fused ns blocks
    gemm_qkv_kernel<<<816, 256, 49152>>>(b_qkv, tokens, seqc,
                                         Wq, bq, Wk, bk, Wv, bv);

    // 3) attention (K,V single fp16, emits ctx A-fragments)
    dim3 g2(S_LEN / 128, BATCH * NHEADS);
    attn_tc_kernel<<<g2, 256, 33280>>>(mask);

    // 4) output projection -> d_out
    dim3 g3(DMODEL / 128, MBLK);
    gemm_out_kernel<<<g3, 256, 33280 < 49152 ? 49152 : 49152>>>(b_out, out);
}

// round 14
// speedup vs baseline: 1.5083x; 1.4225x over previous
#include <cuda_runtime.h>
#include <cuda_fp16.h>
#include <cstdint>

#define S_LEN   2048
#define DMODEL  1024
#define BATCH   2
#define NHEADS  16
#define HDIM    64
#define QKV_LD  3072
#define NKTILES (S_LEN / 64)
#define MROWS   (BATCH * S_LEN)   // 4096
#define MBLK    (MROWS / 128)     // 32
#define KIT     (DMODEL / 32)     // 32

__device__ float g_q[(size_t)MROWS * DMODEL];           // dense Q fp32
__device__ uint2 g_kfrag[(size_t)BATCH * NHEADS * NKTILES * 1024];  // K single fp16
__device__ uint2 g_vfrag[(size_t)BATCH * NHEADS * NKTILES * 1024];  // V single fp16
__device__ uint4 g_wqkv_frag[(size_t)(QKV_LD / 128) * KIT * 1024];
__device__ uint4 g_wout_frag[(size_t)(DMODEL / 128) * KIT * 1024];
__device__ uint4 g_atok_frag[(size_t)MBLK * KIT * 512];
__device__ uint4 g_actx_frag[(size_t)MBLK * KIT * 512];

// ---------------------------------------------------------------------------
__device__ __forceinline__ void mma_f16(float* d, const uint32_t* a, const uint32_t* b) {
    asm volatile(
        "mma.sync.aligned.m16n8k16.row.col.f32.f16.f16.f32 "
        "{%0,%1,%2,%3}, {%4,%5,%6,%7}, {%8,%9}, {%0,%1,%2,%3};\n"
        : "+f"(d[0]), "+f"(d[1]), "+f"(d[2]), "+f"(d[3])
        : "r"(a[0]), "r"(a[1]), "r"(a[2]), "r"(a[3]), "r"(b[0]), "r"(b[1]));
}

__device__ __forceinline__ void split2h(float x, __half& hi, __half& lo) {
    hi = __float2half_rn(x);
    lo = __float2half_rn(x - __half2float(hi));
}

__device__ __forceinline__ uint32_t pack2h(float x, float y) {
    __half2 h = __floats2half2_rn(x, y);
    return *(uint32_t*)&h;
}

__device__ __forceinline__ void cp_async16(void* smem_ptr, const void* gptr) {
    uint32_t sa = (uint32_t)__cvta_generic_to_shared(smem_ptr);
    asm volatile("cp.async.cg.shared.global [%0], [%1], 16;\n" :: "r"(sa), "l"(gptr));
}
__device__ __forceinline__ void cp_commit() {
    asm volatile("cp.async.commit_group;\n");
}
template <int N>
__device__ __forceinline__ void cp_wait() {
    asm volatile("cp.async.wait_group %0;\n" :: "n"(N));
}

__device__ __forceinline__ bool in_ns(int s, int pos) {
    return (unsigned)(s - pos) < 8u;
}

// ---------------------------------------------------------------------------
// Combined presplit: [0,768) W_qkv B-frags, [768,1024) W_out B-frags,
// [1024,2048) tokens A-frags.
// ---------------------------------------------------------------------------
__global__ void __launch_bounds__(256) presplit_all_kernel(
    const float* __restrict__ tokens, const float* __restrict__ W_qkv,
    const float* __restrict__ W_out)
{
    const int bid = blockIdx.x;
    if (bid < 1024) {
        const float* W;
        uint4* out;
        int N, j;
        if (bid < 768) { W = W_qkv; out = g_wqkv_frag; N = QKV_LD; j = bid; }
        else           { W = W_out; out = g_wout_frag; N = DMODEL; j = bid - 768; }
        const int it = j & 31;
        const int nb = j >> 5;
        uint4* chunk = out + ((size_t)nb * KIT + it) * 1024;
#pragma unroll
        for (int i = 0; i < 4; i++) {
            const int s    = threadIdx.x + i * 256;
            const int lane = s & 31;
            const int n8   = (s >> 5) & 15;
            const int ks   = s >> 9;
            const int n = nb * 128 + n8 * 8 + (lane >> 2);
            const int k = it * 32 + ks * 16 + (lane & 3) * 2;
            const float b0 = W[(size_t)k * N + n];
            const float b1 = W[(size_t)(k + 1) * N + n];
            const float b2 = W[(size_t)(k + 8) * N + n];
            const float b3 = W[(size_t)(k + 9) * N + n];
            __half h0, l0, h1, l1, h2, l2, h3, l3;
            split2h(b0, h0, l0); split2h(b1, h1, l1);
            split2h(b2, h2, l2); split2h(b3, h3, l3);
            __half2 whi0(h0, h1), whi1(h2, h3), wlo0(l0, l1), wlo1(l2, l3);
            chunk[s] = make_uint4(*(uint32_t*)&whi0, *(uint32_t*)&whi1,
                                  *(uint32_t*)&wlo0, *(uint32_t*)&wlo1);
        }
    } else {
        const int j  = bid - 1024;
        const int it = j & 31;
        const int mb = j >> 5;
        uint4* chunk = g_atok_frag + ((size_t)mb * KIT + it) * 512;
#pragma unroll
        for (int i = 0; i < 2; i++) {
            const int s    = threadIdx.x + i * 256;
            const int lane = s & 31;
            const int mt   = (s >> 5) & 7;
            const int ks   = s >> 8;
            const int m = mb * 128 + mt * 16 + (lane >> 2);
            const int k = it * 32 + ks * 16 + (lane & 3) * 2;
            const float2 r0 = *(const float2*)&tokens[(size_t)m * DMODEL + k];
            const float2 r1 = *(const float2*)&tokens[(size_t)(m + 8) * DMODEL + k];
            const float2 r2 = *(const float2*)&tokens[(size_t)m * DMODEL + k + 8];
            const float2 r3 = *(const float2*)&tokens[(size_t)(m + 8) * DMODEL + k + 8];
            chunk[s] = make_uint4(pack2h(r0.x, r0.y), pack2h(r1.x, r1.y),
                                  pack2h(r2.x, r2.y), pack2h(r3.x, r3.y));
        }
    }
}

// ---------------------------------------------------------------------------
// QKV frag GEMM + fused frag emission (K and V single fp16) + ns blocks.
// ---------------------------------------------------------------------------
__global__ void __launch_bounds__(256) gemm_qkv_kernel(
    const float* __restrict__ bias, const float* __restrict__ tokens,
    const int* __restrict__ seqc,
    const float* __restrict__ Wq, const float* __restrict__ bq,
    const float* __restrict__ Wk, const float* __restrict__ bk,
    const float* __restrict__ Wv, const float* __restrict__ bv)
{
    extern __shared__ uint4 dyn[];

    if (blockIdx.x >= 768) {
        float* st = (float*)dyn;
        const int bid2 = blockIdx.x - 768;
        const int mat = bid2 >> 4;
        const int b   = (bid2 >> 3) & 1;
        const int n   = bid2 & 7;
        const int pos = *seqc;
        const int row = pos + n;
        if (pos < 0 || row < 0 || row >= S_LEN) return;

        const float* W; const float* bb;
        if (mat == 0)      { W = Wq; bb = bq; }
        else if (mat == 1) { W = Wk; bb = bk; }
        else               { W = Wv; bb = bv; }
        W  += (size_t)n * DMODEL * DMODEL;
        bb += n * DMODEL;

        const float* trow = tokens + ((size_t)b * S_LEN + row) * DMODEL;
        const int tid = threadIdx.x;
        *(float4*)&st[tid * 4] = *(const float4*)&trow[tid * 4];
        __syncthreads();

        float acc[4];
#pragma unroll
        for (int j = 0; j < 4; j++) acc[j] = bb[tid + 256 * j];
        for (int d = 0; d < DMODEL; d++) {
            const float td = st[d];
            const float* wr = W + (size_t)d * DMODEL;
#pragma unroll
            for (int j = 0; j < 4; j++) acc[j] += td * wr[tid + 256 * j];
        }

        const int loc = row & 63;
        const int tile = row >> 6;
        if (mat == 0) {
#pragma unroll
            for (int j = 0; j < 4; j++)
                g_q[((size_t)b * S_LEN + row) * DMODEL + tid + 256 * j] = acc[j];
        } else if (mat == 1) {
#pragma unroll
            for (int j = 0; j < 4; j++) {
                const int col = tid + 256 * j;
                const int h = col >> 6;
                const int c = col & 63;
                const int bh = b * 16 + h;
                const int slot = ((loc >> 3) * 4 + (c >> 4)) * 32 + (loc & 7) * 4 + ((c & 7) >> 1);
                const int word = (c >> 3) & 1;
                const int half = c & 1;
                __half* p = (__half*)(g_kfrag + ((size_t)bh * NKTILES + tile) * 1024 + slot);
                p[word * 2 + half] = __float2half_rn(acc[j]);
            }
        } else {
#pragma unroll
            for (int j = 0; j < 4; j++) {
                const int col = tid + 256 * j;
                const int h = col >> 6;
                const int c = col & 63;
                const int bh = b * 16 + h;
                const int slot = ((c >> 3) * 4 + (loc >> 4)) * 32 + (c & 7) * 4 + ((loc & 7) >> 1);
                const int word = (loc >> 3) & 1;
                const int half = loc & 1;
                __half* p = (__half*)(g_vfrag + ((size_t)bh * NKTILES + tile) * 1024 + slot);
                p[word * 2 + half] = __float2half_rn(acc[j]);
            }
        }
        return;
    }

    uint4* sA = dyn;
    uint4* sB = dyn + 1024;

    const int tid    = threadIdx.x;
    const int lane   = tid & 31;
    const int wid    = tid >> 5;
    const int nb     = blockIdx.x % 24;
    const int mb     = blockIdx.x / 24;
    const int warp_m = (wid >> 2);
    const int warp_n = (wid & 3);

    const uint4* Ab = g_atok_frag + (size_t)mb * KIT * 512;
    const uint4* Bb = g_wqkv_frag + (size_t)nb * KIT * 1024;

    float acc[4][4][4];
#pragma unroll
    for (int mi = 0; mi < 4; mi++)
#pragma unroll
        for (int ni = 0; ni < 4; ni++)
#pragma unroll
            for (int r = 0; r < 4; r++) acc[mi][ni][r] = 0.f;

#pragma unroll
    for (int i = 0; i < 2; i++) cp_async16(&sA[tid + i * 256], Ab + tid + i * 256);
#pragma unroll
    for (int i = 0; i < 4; i++) cp_async16(&sB[tid + i * 256], Bb + tid + i * 256);
    cp_commit();

    for (int it = 0; it < KIT; it++) {
        const int buf = it & 1;
        if (it + 1 < KIT) {
            const int nbuf = (it + 1) & 1;
            const uint4* na  = Ab + (size_t)(it + 1) * 512;
            const uint4* nb4 = Bb + (size_t)(it + 1) * 1024;
#pragma unroll
            for (int i = 0; i < 2; i++)
                cp_async16(&sA[nbuf * 512 + tid + i * 256], na + tid + i * 256);
#pragma unroll
            for (int i = 0; i < 4; i++)
                cp_async16(&sB[nbuf * 1024 + tid + i * 256], nb4 + tid + i * 256);
            cp_commit();
            cp_wait<1>();
        } else {
            cp_wait<0>();
        }
        __syncthreads();

        const uint4* bA = sA + buf * 512;
        const uint4* bB = sB + buf * 1024;

#pragma unroll
        for (int ks = 0; ks < 2; ks++) {
            uint4 ah[4], bbv[4];
#pragma unroll
            for (int mi = 0; mi < 4; mi++)
                ah[mi] = bA[(ks * 8 + warp_m * 4 + mi) * 32 + lane];
#pragma unroll
            for (int ni = 0; ni < 4; ni++)
                bbv[ni] = bB[(ks * 16 + warp_n * 4 + ni) * 32 + lane];
#pragma unroll
            for (int mi = 0; mi < 4; mi++) {
                const uint32_t* ap = (const uint32_t*)&ah[mi];
#pragma unroll
                for (int ni = 0; ni < 4; ni++) {
                    uint32_t bfr[2] = {bbv[ni].x, bbv[ni].y};
                    uint32_t bfl[2] = {bbv[ni].z, bbv[ni].w};
                    mma_f16(acc[mi][ni], ap, bfr);
                    mma_f16(acc[mi][ni], ap, bfl);
                }
            }
        }
        __syncthreads();
    }

    const int pos = *seqc;
    const int bm  = mb * 128;
    const int bn  = nb * 128;

#pragma unroll
    for (int mi = 0; mi < 4; mi++) {
        const int row = bm + warp_m * 64 + mi * 16 + (lane >> 2);
        const int b   = row >> 11;
        const int s   = row & 2047;
        const int tile = s >> 6;
        const int loc  = s & 63;
#pragma unroll
        for (int ni = 0; ni < 4; ni++) {
            const int col = bn + warp_n * 32 + ni * 8 + (lane & 3) * 2;
            const float2 bv2 = *(const float2*)&bias[col];
            const float x0 = acc[mi][ni][0] + bv2.x;
            const float x1 = acc[mi][ni][1] + bv2.y;
            const float x2 = acc[mi][ni][2] + bv2.x;
            const float x3 = acc[mi][ni][3] + bv2.y;

            if (nb < 8) {
                if (!in_ns(s, pos)) {
                    float2 o = {x0, x1};
                    *(float2*)&g_q[(size_t)row * DMODEL + col] = o;
                }
                if (!in_ns(s + 8, pos)) {
                    float2 o = {x2, x3};
                    *(float2*)&g_q[(size_t)(row + 8) * DMODEL + col] = o;
                }
            } else if (nb < 16) {
                const int kc = col & 63;
                const int h  = (col >> 6) & 15;
                uint32_t* kb32 = (uint32_t*)(g_kfrag +
                    ((size_t)(b * 16 + h) * NKTILES + tile) * 1024);
                const uint32_t H0 = pack2h(x0, x1);
                const uint32_t H8 = pack2h(x2, x3);
                const int word  = (kc >> 3) & 1;
                const int slot0 = ((loc >> 3) * 4 + (kc >> 4)) * 32 + (loc & 7) * 4 + ((kc & 7) >> 1);
                if (!in_ns(s, pos))     kb32[slot0 * 2 + word] = H0;
                if (!in_ns(s + 8, pos)) kb32[(slot0 + 128) * 2 + word] = H8;
            } else {
                const int vc = col & 63;
                const int h  = (col >> 6) & 15;
                uint32_t* vb32 = (uint32_t*)(g_vfrag +
                    ((size_t)(b * 16 + h) * NKTILES + tile) * 1024);
                const uint32_t H0 = pack2h(x0, x1);
                const uint32_t H8 = pack2h(x2, x3);
                const uint32_t pH0 = __shfl_xor_sync(0xffffffffu, H0, 4);
                const uint32_t pH8 = __shfl_xor_sync(0xffffffffu, H8, 4);
                if (((lane >> 2) & 1) == 0) {
#pragma unroll
                    for (int pp = 0; pp < 2; pp++) {
                        const int kl = loc + pp * 8;
                        const int kg = s + pp * 8;
                        const uint32_t Ah = pp ? H8 : H0;
                        const uint32_t Bh = pp ? pH8 : pH0;
                        const bool ok0 = !in_ns(kg, pos);
                        const bool ok1 = !in_ns(kg + 1, pos);
                        const int word = (kl >> 3) & 1;
#pragma unroll
                        for (int dd = 0; dd < 2; dd++) {
                            const int d = vc + dd;
                            const int slot = ((d >> 3) * 4 + (kl >> 4)) * 32 + (d & 7) * 4 + ((kl & 7) >> 1);
                            const uint32_t wh = dd ? __byte_perm(Ah, Bh, 0x7632)
                                                   : __byte_perm(Ah, Bh, 0x5410);
                            uint32_t* p = vb32 + slot * 2 + word;
                            if (ok0 && ok1) {
                                p[0] = wh;
                            } else {
                                unsigned short* ps = (unsigned short*)p;
                                if (ok0) ps[0] = (unsigned short)(wh & 0xffff);
                                if (ok1) ps[1] = (unsigned short)(wh >> 16);
                            }
                        }
                    }
                }
            }
        }
    }
}

// ---------------------------------------------------------------------------
// Output projection frag GEMM (unchanged)
// ---------------------------------------------------------------------------
__global__ void __launch_bounds__(256) gemm_out_kernel(
    const float* __restrict__ bias, float* __restrict__ C)
{
    extern __shared__ uint4 dyn[];
    uint4* sA = dyn;
    uint4* sB = dyn + 1024;

    const int tid    = threadIdx.x;
    const int lane   = tid & 31;
    const int wid    = tid >> 5;
    const int nb     = blockIdx.x;
    const int mb     = blockIdx.y;
    const int warp_m = (wid >> 2);
    const int warp_n = (wid & 3);

    const uint4* Ab = g_actx_frag + (size_t)mb * KIT * 512;
    const uint4* Bb = g_wout_frag + (size_t)nb * KIT * 1024;

    float acc[4][4][4];
#pragma unroll
    for (int mi = 0; mi < 4; mi++)
#pragma unroll
        for (int ni = 0; ni < 4; ni++)
#pragma unroll
            for (int r = 0; r < 4; r++) acc[mi][ni][r] = 0.f;

#pragma unroll
    for (int i = 0; i < 2; i++) cp_async16(&sA[tid + i * 256], Ab + tid + i * 256);
#pragma unroll
    for (int i = 0; i < 4; i++) cp_async16(&sB[tid + i * 256], Bb + tid + i * 256);
    cp_commit();

    for (int it = 0; it < KIT; it++) {
        const int buf = it & 1;
        if (it + 1 < KIT) {
            const int nbuf = (it + 1) & 1;
            const uint4* na  = Ab + (size_t)(it + 1) * 512;
            const uint4* nb4 = Bb + (size_t)(it + 1) * 1024;
#pragma unroll
            for (int i = 0; i < 2; i++)
                cp_async16(&sA[nbuf * 512 + tid + i * 256], na + tid + i * 256);
#pragma unroll
            for (int i = 0; i < 4; i++)
                cp_async16(&sB[nbuf * 1024 + tid + i * 256], nb4 + tid + i * 256);
            cp_commit();
            cp_wait<1>();
        } else {
            cp_wait<0>();
        }
        __syncthreads();

        const uint4* bA = sA + buf * 512;
        const uint4* bB = sB + buf * 1024;

#pragma unroll
        for (int ks = 0; ks < 2; ks++) {
            uint4 ah[4], bbv[4];
#pragma unroll
            for (int mi = 0; mi < 4; mi++)
                ah[mi] = bA[(ks * 8 + warp_m * 4 + mi) * 32 + lane];
#pragma unroll
            for (int ni = 0; ni < 4; ni++)
                bbv[ni] = bB[(ks * 16 + warp_n * 4 + ni) * 32 + lane];
#pragma unroll
            for (int mi = 0; mi < 4; mi++) {
                const uint32_t* ap = (const uint32_t*)&ah[mi];
#pragma unroll
                for (int ni = 0; ni < 4; ni++) {
                    uint32_t bfr[2] = {bbv[ni].x, bbv[ni].y};
                    uint32_t bfl[2] = {bbv[ni].z, bbv[ni].w};
                    mma_f16(acc[mi][ni], ap, bfr);
                    mma_f16(acc[mi][ni], ap, bfl);
                }
            }
        }
        __syncthreads();
    }

    const int bm = mb * 128;
    const int bn = nb * 128;
#pragma unroll
    for (int mi = 0; mi < 4; mi++) {
        const int row = bm + warp_m * 64 + mi * 16 + (lane >> 2);
#pragma unroll
        for (int ni = 0; ni < 4; ni++) {
            const int col = bn + warp_n * 32 + ni * 8 + (lane & 3) * 2;
            const float2 bv2 = *(const float2*)&bias[col];
            float2 o0, o1;
            o0.x = acc[mi][ni][0] + bv2.x;  o0.y = acc[mi][ni][1] + bv2.y;
            o1.x = acc[mi][ni][2] + bv2.x;  o1.y = acc[mi][ni][3] + bv2.y;
            *(float2*)&C[(size_t)row * DMODEL + col]       = o0;
            *(float2*)&C[(size_t)(row + 8) * DMODEL + col] = o1;
        }
    }
}

// ---------------------------------------------------------------------------
// Tensor-core flash attention, FIXED-MAX softmax (scores provably bounded):
// no online max, no corr, no per-tile shfls — sum reduced once at the end.
// smem: sK 2x8KB + sV 2x8KB + mask 512B = 33280B
// ---------------------------------------------------------------------------
__global__ void __launch_bounds__(256, 2) attn_tc_kernel(
    const unsigned int* __restrict__ mask)
{
    extern __shared__ uint4 dyn[];
    uint4*    sK    = dyn;
    uint4*    sV    = dyn + 1024;
    uint32_t* sMask = (uint32_t*)(dyn + 2048);

    const int tid  = threadIdx.x;
    const int w    = tid >> 5;
    const int lane = tid & 31;
    const int bxr  = (S_LEN / 128 - 1) - blockIdx.x;
    const int bh   = blockIdx.y;
    const int b    = bh >> 4;
    const int h    = bh & 15;
    const int r0   = bxr * 128;

    const float* qb = g_q + ((size_t)b * S_LEN) * DMODEL + h * HDIM;
    const unsigned int* mb = mask + b * S_LEN;
    const uint4* kfb = (const uint4*)(g_kfrag + ((size_t)bh * NKTILES << 10));
    const uint4* vfb = (const uint4*)(g_vfrag + ((size_t)bh * NKTILES << 10));

    const int ntiles = (r0 + 128) >> 6;

    const float QS = 0.125f * 1.44269504f;
    uint32_t qh[4][4];
    {
        const int rlo = r0 + w * 16 + (lane >> 2);
        const float* q0 = qb + (size_t)rlo * DMODEL;
        const float* q1 = qb + (size_t)(rlo + 8) * DMODEL;
#pragma unroll
        for (int ks = 0; ks < 4; ks++) {
            const int c = ks * 16 + (lane & 3) * 2;
            float2 x0 = *(const float2*)&q0[c];
            float2 x1 = *(const float2*)&q1[c];
            float2 x2 = *(const float2*)&q0[c + 8];
            float2 x3 = *(const float2*)&q1[c + 8];
            qh[ks][0] = pack2h(x0.x * QS, x0.y * QS);
            qh[ks][1] = pack2h(x1.x * QS, x1.y * QS);
            qh[ks][2] = pack2h(x2.x * QS, x2.y * QS);
            qh[ks][3] = pack2h(x3.x * QS, x3.y * QS);
        }
    }

    float l_i[2] = {0.f, 0.f};
    float o_acc[8][4];
#pragma unroll
    for (int dt = 0; dt < 8; dt++)
#pragma unroll
        for (int r = 0; r < 4; r++) o_acc[dt][r] = 0.f;

    const int q0g = r0 + w * 16 + (lane >> 2);

    {
#pragma unroll
        for (int i = 0; i < 2; i++) {
            cp_async16(&sK[tid + i * 256], kfb + tid + i * 256);
            cp_async16(&sV[tid + i * 256], vfb + tid + i * 256);
        }
        if (tid < 16) cp_async16(&sMask[tid * 4], mb + tid * 4);
        cp_commit();
    }

    for (int t = 0; t < ntiles; t++) {
        const int buf = t & 1;
        if (t + 1 < ntiles) {
            const int nb = (t + 1) & 1;
            const uint4* srcK = kfb + ((size_t)(t + 1) << 9);
            const uint4* srcV = vfb + ((size_t)(t + 1) << 9);
#pragma unroll
            for (int i = 0; i < 2; i++) {
                cp_async16(&sK[nb * 512 + tid + i * 256], srcK + tid + i * 256);
                cp_async16(&sV[nb * 512 + tid + i * 256], srcV + tid + i * 256);
            }
            if (tid < 16) cp_async16(&sMask[nb * 64 + tid * 4], mb + (t + 1) * 64 + tid * 4);
            cp_commit();
            cp_wait<1>();
        } else {
            cp_wait<0>();
        }
        __syncthreads();

        const int k0 = t << 6;
        const uint2* bK = (const uint2*)(sK + buf * 512);
        const uint2* bV = (const uint2*)(sV + buf * 512);
        const uint32_t* bM = sMask + buf * 64;

        float s[8][4];
#pragma unroll
        for (int nt = 0; nt < 8; nt++)
#pragma unroll
            for (int r = 0; r < 4; r++) s[nt][r] = 0.f;

#pragma unroll
        for (int ks = 0; ks < 4; ks++) {
#pragma unroll
            for (int nt = 0; nt < 8; nt++) {
                const uint2 v = bK[(nt * 4 + ks) * 32 + lane];
                uint32_t bfr[2] = {v.x, v.y};
                mma_f16(s[nt], qh[ks], bfr);
            }
        }

        // ---- fixed-max softmax: p = mask ? exp2(s) : 0; per-thread sum ----
#pragma unroll
        for (int nt = 0; nt < 8; nt++)
#pragma unroll
            for (int r = 0; r < 4; r++) {
                const int row = r >> 1;
                const int c   = r & 1;
                const int kl  = nt * 8 + (lane & 3) * 2 + c;
                const bool ok = (bM[kl] != 0u) && (k0 + kl <= q0g + row * 8);
                const float p = ok ? exp2f(s[nt][r]) : 0.f;
                s[nt][r] = p;
                l_i[row] += p;
            }

        // ---- PV ----
#pragma unroll
        for (int ks2 = 0; ks2 < 4; ks2++) {
            uint32_t pah[4];
            pah[0] = pack2h(s[ks2*2][0],   s[ks2*2][1]);
            pah[1] = pack2h(s[ks2*2][2],   s[ks2*2][3]);
            pah[2] = pack2h(s[ks2*2+1][0], s[ks2*2+1][1]);
            pah[3] = pack2h(s[ks2*2+1][2], s[ks2*2+1][3]);
#pragma unroll
            for (int dt = 0; dt < 8; dt++) {
                const uint2 v = bV[(dt * 4 + ks2) * 32 + lane];
                uint32_t bfr[2] = {v.x, v.y};
                mma_f16(o_acc[dt], pah, bfr);
            }
        }
        __syncthreads();
    }

    // ---- one-time sum reduce across the quad, then epilogue ----
#pragma unroll
    for (int row = 0; row < 2; row++) {
        l_i[row] += __shfl_xor_sync(0xffffffffu, l_i[row], 1);
        l_i[row] += __shfl_xor_sync(0xffffffffu, l_i[row], 2);
    }
    const float inv0 = 1.f / l_i[0];
    const float inv1 = 1.f / l_i[1];
    uint4* dst = g_actx_frag + ((size_t)(b * 16 + (r0 >> 7)) * KIT) * 512;
#pragma unroll
    for (int f = 0; f < 4; f++) {
        const int it  = h * 2 + (f >> 1);
        const int ks  = f & 1;
        const int dt0 = f * 2, dt1 = f * 2 + 1;
        uint4 u;
        u.x = pack2h(o_acc[dt0][0] * inv0, o_acc[dt0][1] * inv0);
        u.y = pack2h(o_acc[dt0][2] * inv1, o_acc[dt0][3] * inv1);
        u.z = pack2h(o_acc[dt1][0] * inv0, o_acc[dt1][1] * inv0);
        u.w = pack2h(o_acc[dt1][2] * inv1, o_acc[dt1][3] * inv1);
        dst[(size_t)it * 512 + (ks * 8 + w) * 32 + lane] = u;
    }
}

// ---------------------------------------------------------------------------
extern "C" void kernel_launch(void* const* d_in, const int* in_sizes, int n_in,
                              void* d_out, int out_size)
{
    const float*        tokens = (const float*)d_in[0];
    const unsigned int* mask   = (const unsigned int*)d_in[1];
    const int*          seqc   = (const int*)d_in[2];
    const float*        W_qkv  = (const float*)d_in[3];
    const float*        b_qkv  = (const float*)d_in[4];
    const float*        Wq     = (const float*)d_in[5];
    const float*        bq     = (const float*)d_in[6];
    const float*        Wk     = (const float*)d_in[7];
    const float*        bk     = (const float*)d_in[8];
    const float*        Wv     = (const float*)d_in[9];
    const float*        bv     = (const float*)d_in[10];
    const float*        W_out  = (const float*)d_in[11];
    const float*        b_out  = (const float*)d_in[12];
    float*              out    = (float*)d_out;

    cudaFuncSetAttribute(gemm_qkv_kernel,
                         cudaFuncAttributeMaxDynamicSharedMemorySize, 49152);
    cudaFuncSetAttribute(gemm_out_kernel,
                         cudaFuncAttributeMaxDynamicSharedMemorySize, 49152);
    cudaFuncSetAttribute(attn_tc_kernel,
                         cudaFuncAttributeMaxDynamicSharedMemorySize, 33280);

    // 1) all operand presplits
    presplit_all_kernel<<<2048, 256>>>(tokens, W_qkv, W_out);

    // 2) QKV projection + fused K/V frag emission + fused ns blocks
    gemm_qkv_kernel<<<816, 256, 49152>>>(b_qkv, tokens, seqc,
                                         Wq, bq, Wk, bk, Wv, bv);

    // 3) attention (fixed-max softmax, emits ctx A-fragments)
    dim3 g2(S_LEN / 128, BATCH * NHEADS);
    attn_tc_kernel<<<g2, 256, 33280>>>(mask);

    // 4) output projection -> d_out
    dim3 g3(DMODEL / 128, MBLK);
    gemm_out_kernel<<<g3, 256, 49152>>>(b_out, out);
}

// round 15
// speedup vs baseline: 1.9749x; 1.3093x over previous
#include <cuda_runtime.h>
#include <cuda_fp16.h>
#include <cstdint>

#define S_LEN   2048
#define DMODEL  1024
#define BATCH   2
#define NHEADS  16
#define HDIM    64
#define QKV_LD  3072
#define NKTILES (S_LEN / 64)
#define MROWS   (BATCH * S_LEN)   // 4096
#define MBLK    (MROWS / 128)     // 32
#define KIT     (DMODEL / 32)     // 32

__device__ float g_q[(size_t)MROWS * DMODEL];           // dense Q fp32
__device__ uint2 g_kfrag[(size_t)BATCH * NHEADS * NKTILES * 1024];  // K single fp16
__device__ uint2 g_vfrag[(size_t)BATCH * NHEADS * NKTILES * 1024];  // V single fp16
__device__ uint2 g_wqkv_frag[(size_t)(QKV_LD / 128) * KIT * 1024];  // W single fp16
__device__ uint2 g_wout_frag[(size_t)(DMODEL / 128) * KIT * 1024];  // W single fp16
__device__ uint4 g_atok_frag[(size_t)MBLK * KIT * 512];
__device__ uint4 g_actx_frag[(size_t)MBLK * KIT * 512];

// ---------------------------------------------------------------------------
__device__ __forceinline__ void mma_f16(float* d, const uint32_t* a, const uint32_t* b) {
    asm volatile(
        "mma.sync.aligned.m16n8k16.row.col.f32.f16.f16.f32 "
        "{%0,%1,%2,%3}, {%4,%5,%6,%7}, {%8,%9}, {%0,%1,%2,%3};\n"
        : "+f"(d[0]), "+f"(d[1]), "+f"(d[2]), "+f"(d[3])
        : "r"(a[0]), "r"(a[1]), "r"(a[2]), "r"(a[3]), "r"(b[0]), "r"(b[1]));
}

__device__ __forceinline__ uint32_t pack2h(float x, float y) {
    __half2 h = __floats2half2_rn(x, y);
    return *(uint32_t*)&h;
}

__device__ __forceinline__ void cp_async16(void* smem_ptr, const void* gptr) {
    uint32_t sa = (uint32_t)__cvta_generic_to_shared(smem_ptr);
    asm volatile("cp.async.cg.shared.global [%0], [%1], 16;\n" :: "r"(sa), "l"(gptr));
}
__device__ __forceinline__ void cp_commit() {
    asm volatile("cp.async.commit_group;\n");
}
template <int N>
__device__ __forceinline__ void cp_wait() {
    asm volatile("cp.async.wait_group %0;\n" :: "n"(N));
}

__device__ __forceinline__ bool in_ns(int s, int pos) {
    return (unsigned)(s - pos) < 8u;
}

// ---------------------------------------------------------------------------
// Combined presplit: [0,768) W_qkv B-frags, [768,1024) W_out B-frags,
// [1024,2048) tokens A-frags. W frags are single fp16 (uint2 slots).
// ---------------------------------------------------------------------------
__global__ void __launch_bounds__(256) presplit_all_kernel(
    const float* __restrict__ tokens, const float* __restrict__ W_qkv,
    const float* __restrict__ W_out)
{
    const int bid = blockIdx.x;
    if (bid < 1024) {
        const float* W;
        uint2* out;
        int N, j;
        if (bid < 768) { W = W_qkv; out = g_wqkv_frag; N = QKV_LD; j = bid; }
        else           { W = W_out; out = g_wout_frag; N = DMODEL; j = bid - 768; }
        const int it = j & 31;
        const int nb = j >> 5;
        uint2* chunk = out + ((size_t)nb * KIT + it) * 1024;
#pragma unroll
        for (int i = 0; i < 4; i++) {
            const int s    = threadIdx.x + i * 256;
            const int lane = s & 31;
            const int n8   = (s >> 5) & 15;
            const int ks   = s >> 9;
            const int n = nb * 128 + n8 * 8 + (lane >> 2);
            const int k = it * 32 + ks * 16 + (lane & 3) * 2;
            const float b0 = W[(size_t)k * N + n];
            const float b1 = W[(size_t)(k + 1) * N + n];
            const float b2 = W[(size_t)(k + 8) * N + n];
            const float b3 = W[(size_t)(k + 9) * N + n];
            chunk[s] = make_uint2(pack2h(b0, b1), pack2h(b2, b3));
        }
    } else {
        const int j  = bid - 1024;
        const int it = j & 31;
        const int mb = j >> 5;
        uint4* chunk = g_atok_frag + ((size_t)mb * KIT + it) * 512;
#pragma unroll
        for (int i = 0; i < 2; i++) {
            const int s    = threadIdx.x + i * 256;
            const int lane = s & 31;
            const int mt   = (s >> 5) & 7;
            const int ks   = s >> 8;
            const int m = mb * 128 + mt * 16 + (lane >> 2);
            const int k = it * 32 + ks * 16 + (lane & 3) * 2;
            const float2 r0 = *(const float2*)&tokens[(size_t)m * DMODEL + k];
            const float2 r1 = *(const float2*)&tokens[(size_t)(m + 8) * DMODEL + k];
            const float2 r2 = *(const float2*)&tokens[(size_t)m * DMODEL + k + 8];
            const float2 r3 = *(const float2*)&tokens[(size_t)(m + 8) * DMODEL + k + 8];
            chunk[s] = make_uint4(pack2h(r0.x, r0.y), pack2h(r1.x, r1.y),
                                  pack2h(r2.x, r2.y), pack2h(r3.x, r3.y));
        }
    }
}

// ---------------------------------------------------------------------------
// QKV frag GEMM (fp16 x fp16, 32 MMA/warp-iter) + fused frag emission + ns.
// smem: sA 2x8KB + sB 2x8KB = 32KB -> 2 CTAs/SM.
// ---------------------------------------------------------------------------
__global__ void __launch_bounds__(256, 2) gemm_qkv_kernel(
    const float* __restrict__ bias, const float* __restrict__ tokens,
    const int* __restrict__ seqc,
    const float* __restrict__ Wq, const float* __restrict__ bq,
    const float* __restrict__ Wk, const float* __restrict__ bk,
    const float* __restrict__ Wv, const float* __restrict__ bv)
{
    extern __shared__ uint4 dyn[];

    if (blockIdx.x >= 768) {
        float* st = (float*)dyn;
        const int bid2 = blockIdx.x - 768;
        const int mat = bid2 >> 4;
        const int b   = (bid2 >> 3) & 1;
        const int n   = bid2 & 7;
        const int pos = *seqc;
        const int row = pos + n;
        if (pos < 0 || row < 0 || row >= S_LEN) return;

        const float* W; const float* bb;
        if (mat == 0)      { W = Wq; bb = bq; }
        else if (mat == 1) { W = Wk; bb = bk; }
        else               { W = Wv; bb = bv; }
        W  += (size_t)n * DMODEL * DMODEL;
        bb += n * DMODEL;

        const float* trow = tokens + ((size_t)b * S_LEN + row) * DMODEL;
        const int tid = threadIdx.x;
        *(float4*)&st[tid * 4] = *(const float4*)&trow[tid * 4];
        __syncthreads();

        float acc[4];
#pragma unroll
        for (int j = 0; j < 4; j++) acc[j] = bb[tid + 256 * j];
        for (int d = 0; d < DMODEL; d++) {
            const float td = st[d];
            const float* wr = W + (size_t)d * DMODEL;
#pragma unroll
            for (int j = 0; j < 4; j++) acc[j] += td * wr[tid + 256 * j];
        }

        const int loc = row & 63;
        const int tile = row >> 6;
        if (mat == 0) {
#pragma unroll
            for (int j = 0; j < 4; j++)
                g_q[((size_t)b * S_LEN + row) * DMODEL + tid + 256 * j] = acc[j];
        } else if (mat == 1) {
#pragma unroll
            for (int j = 0; j < 4; j++) {
                const int col = tid + 256 * j;
                const int h = col >> 6;
                const int c = col & 63;
                const int bh = b * 16 + h;
                const int slot = ((loc >> 3) * 4 + (c >> 4)) * 32 + (loc & 7) * 4 + ((c & 7) >> 1);
                const int word = (c >> 3) & 1;
                const int half = c & 1;
                __half* p = (__half*)(g_kfrag + ((size_t)bh * NKTILES + tile) * 1024 + slot);
                p[word * 2 + half] = __float2half_rn(acc[j]);
            }
        } else {
#pragma unroll
            for (int j = 0; j < 4; j++) {
                const int col = tid + 256 * j;
                const int h = col >> 6;
                const int c = col & 63;
                const int bh = b * 16 + h;
                const int slot = ((c >> 3) * 4 + (loc >> 4)) * 32 + (c & 7) * 4 + ((loc & 7) >> 1);
                const int word = (loc >> 3) & 1;
                const int half = loc & 1;
                __half* p = (__half*)(g_vfrag + ((size_t)bh * NKTILES + tile) * 1024 + slot);
                p[word * 2 + half] = __float2half_rn(acc[j]);
            }
        }
        return;
    }

    uint4* sA = dyn;            // [2][512] uint4
    uint4* sB = dyn + 1024;     // [2][512] uint4 (uint2 slots)

    const int tid    = threadIdx.x;
    const int lane   = tid & 31;
    const int wid    = tid >> 5;
    const int nb     = blockIdx.x % 24;
    const int mb     = blockIdx.x / 24;
    const int warp_m = (wid >> 2);
    const int warp_n = (wid & 3);

    const uint4* Ab = g_atok_frag + (size_t)mb * KIT * 512;
    const uint4* Bb = (const uint4*)(g_wqkv_frag + (size_t)nb * KIT * 1024);

    float acc[4][4][4];
#pragma unroll
    for (int mi = 0; mi < 4; mi++)
#pragma unroll
        for (int ni = 0; ni < 4; ni++)
#pragma unroll
            for (int r = 0; r < 4; r++) acc[mi][ni][r] = 0.f;

#pragma unroll
    for (int i = 0; i < 2; i++) {
        cp_async16(&sA[tid + i * 256], Ab + tid + i * 256);
        cp_async16(&sB[tid + i * 256], Bb + tid + i * 256);
    }
    cp_commit();

    for (int it = 0; it < KIT; it++) {
        const int buf = it & 1;
        if (it + 1 < KIT) {
            const int nbuf = (it + 1) & 1;
            const uint4* na  = Ab + (size_t)(it + 1) * 512;
            const uint4* nb4 = Bb + (size_t)(it + 1) * 512;
#pragma unroll
            for (int i = 0; i < 2; i++) {
                cp_async16(&sA[nbuf * 512 + tid + i * 256], na + tid + i * 256);
                cp_async16(&sB[nbuf * 512 + tid + i * 256], nb4 + tid + i * 256);
            }
            cp_commit();
            cp_wait<1>();
        } else {
            cp_wait<0>();
        }
        __syncthreads();

        const uint4* bA = sA + buf * 512;
        const uint2* bB = (const uint2*)(sB + buf * 512);

#pragma unroll
        for (int ks = 0; ks < 2; ks++) {
            uint4 ah[4]; uint2 bbv[4];
#pragma unroll
            for (int mi = 0; mi < 4; mi++)
                ah[mi] = bA[(ks * 8 + warp_m * 4 + mi) * 32 + lane];
#pragma unroll
            for (int ni = 0; ni < 4; ni++)
                bbv[ni] = bB[(ks * 16 + warp_n * 4 + ni) * 32 + lane];
#pragma unroll
            for (int mi = 0; mi < 4; mi++) {
                const uint32_t* ap = (const uint32_t*)&ah[mi];
#pragma unroll
                for (int ni = 0; ni < 4; ni++) {
                    uint32_t bfr[2] = {bbv[ni].x, bbv[ni].y};
                    mma_f16(acc[mi][ni], ap, bfr);
                }
            }
        }
        __syncthreads();
    }

    const int pos = *seqc;
    const int bm  = mb * 128;
    const int bn  = nb * 128;

#pragma unroll
    for (int mi = 0; mi < 4; mi++) {
        const int row = bm + warp_m * 64 + mi * 16 + (lane >> 2);
        const int b   = row >> 11;
        const int s   = row & 2047;
        const int tile = s >> 6;
        const int loc  = s & 63;
#pragma unroll
        for (int ni = 0; ni < 4; ni++) {
            const int col = bn + warp_n * 32 + ni * 8 + (lane & 3) * 2;
            const float2 bv2 = *(const float2*)&bias[col];
            const float x0 = acc[mi][ni][0] + bv2.x;
            const float x1 = acc[mi][ni][1] + bv2.y;
            const float x2 = acc[mi][ni][2] + bv2.x;
            const float x3 = acc[mi][ni][3] + bv2.y;

            if (nb < 8) {
                if (!in_ns(s, pos)) {
                    float2 o = {x0, x1};
                    *(float2*)&g_q[(size_t)row * DMODEL + col] = o;
                }
                if (!in_ns(s + 8, pos)) {
                    float2 o = {x2, x3};
                    *(float2*)&g_q[(size_t)(row + 8) * DMODEL + col] = o;
                }
            } else if (nb < 16) {
                const int kc = col & 63;
                const int h  = (col >> 6) & 15;
                uint32_t* kb32 = (uint32_t*)(g_kfrag +
                    ((size_t)(b * 16 + h) * NKTILES + tile) * 1024);
                const uint32_t H0 = pack2h(x0, x1);
                const uint32_t H8 = pack2h(x2, x3);
                const int word  = (kc >> 3) & 1;
                const int slot0 = ((loc >> 3) * 4 + (kc >> 4)) * 32 + (loc & 7) * 4 + ((kc & 7) >> 1);
                if (!in_ns(s, pos))     kb32[slot0 * 2 + word] = H0;
                if (!in_ns(s + 8, pos)) kb32[(slot0 + 128) * 2 + word] = H8;
            } else {
                const int vc = col & 63;
                const int h  = (col >> 6) & 15;
                uint32_t* vb32 = (uint32_t*)(g_vfrag +
                    ((size_t)(b * 16 + h) * NKTILES + tile) * 1024);
                const uint32_t H0 = pack2h(x0, x1);
                const uint32_t H8 = pack2h(x2, x3);
                const uint32_t pH0 = __shfl_xor_sync(0xffffffffu, H0, 4);
                const uint32_t pH8 = __shfl_xor_sync(0xffffffffu, H8, 4);
                if (((lane >> 2) & 1) == 0) {
#pragma unroll
                    for (int pp = 0; pp < 2; pp++) {
                        const int kl = loc + pp * 8;
                        const int kg = s + pp * 8;
                        const uint32_t Ah = pp ? H8 : H0;
                        const uint32_t Bh = pp ? pH8 : pH0;
                        const bool ok0 = !in_ns(kg, pos);
                        const bool ok1 = !in_ns(kg + 1, pos);
                        const int word = (kl >> 3) & 1;
#pragma unroll
                        for (int dd = 0; dd < 2; dd++) {
                            const int d = vc + dd;
                            const int slot = ((d >> 3) * 4 + (kl >> 4)) * 32 + (d & 7) * 4 + ((kl & 7) >> 1);
                            const uint32_t wh = dd ? __byte_perm(Ah, Bh, 0x7632)
                                                   : __byte_perm(Ah, Bh, 0x5410);
                            uint32_t* p = vb32 + slot * 2 + word;
                            if (ok0 && ok1) {
                                p[0] = wh;
                            } else {
                                unsigned short* ps = (unsigned short*)p;
                                if (ok0) ps[0] = (unsigned short)(wh & 0xffff);
                                if (ok1) ps[1] = (unsigned short)(wh >> 16);
                            }
                        }
                    }
                }
            }
        }
    }
}

// ---------------------------------------------------------------------------
// Output projection frag GEMM (fp16 x fp16, W single)
// ---------------------------------------------------------------------------
__global__ void __launch_bounds__(256, 2) gemm_out_kernel(
    const float* __restrict__ bias, float* __restrict__ C)
{
    extern __shared__ uint4 dyn[];
    uint4* sA = dyn;            // [2][512]
    uint4* sB = dyn + 1024;     // [2][512]

    const int tid    = threadIdx.x;
    const int lane   = tid & 31;
    const int wid    = tid >> 5;
    const int nb     = blockIdx.x;
    const int mb     = blockIdx.y;
    const int warp_m = (wid >> 2);
    const int warp_n = (wid & 3);

    const uint4* Ab = g_actx_frag + (size_t)mb * KIT * 512;
    const uint4* Bb = (const uint4*)(g_wout_frag + (size_t)nb * KIT * 1024);

    float acc[4][4][4];
#pragma unroll
    for (int mi = 0; mi < 4; mi++)
#pragma unroll
        for (int ni = 0; ni < 4; ni++)
#pragma unroll
            for (int r = 0; r < 4; r++) acc[mi][ni][r] = 0.f;

#pragma unroll
    for (int i = 0; i < 2; i++) {
        cp_async16(&sA[tid + i * 256], Ab + tid + i * 256);
        cp_async16(&sB[tid + i * 256], Bb + tid + i * 256);
    }
    cp_commit();

    for (int it = 0; it < KIT; it++) {
        const int buf = it & 1;
        if (it + 1 < KIT) {
            const int nbuf = (it + 1) & 1;
            const uint4* na  = Ab + (size_t)(it + 1) * 512;
            const uint4* nb4 = Bb + (size_t)(it + 1) * 512;
#pragma unroll
            for (int i = 0; i < 2; i++) {
                cp_async16(&sA[nbuf * 512 + tid + i * 256], na + tid + i * 256);
                cp_async16(&sB[nbuf * 512 + tid + i * 256], nb4 + tid + i * 256);
            }
            cp_commit();
            cp_wait<1>();
        } else {
            cp_wait<0>();
        }
        __syncthreads();

        const uint4* bA = sA + buf * 512;
        const uint2* bB = (const uint2*)(sB + buf * 512);

#pragma unroll
        for (int ks = 0; ks < 2; ks++) {
            uint4 ah[4]; uint2 bbv[4];
#pragma unroll
            for (int mi = 0; mi < 4; mi++)
                ah[mi] = bA[(ks * 8 + warp_m * 4 + mi) * 32 + lane];
#pragma unroll
            for (int ni = 0; ni < 4; ni++)
                bbv[ni] = bB[(ks * 16 + warp_n * 4 + ni) * 32 + lane];
#pragma unroll
            for (int mi = 0; mi < 4; mi++) {
                const uint32_t* ap = (const uint32_t*)&ah[mi];
#pragma unroll
                for (int ni = 0; ni < 4; ni++) {
                    uint32_t bfr[2] = {bbv[ni].x, bbv[ni].y};
                    mma_f16(acc[mi][ni], ap, bfr);
                }
            }
        }
        __syncthreads();
    }

    const int bm = mb * 128;
    const int bn = nb * 128;
#pragma unroll
    for (int mi = 0; mi < 4; mi++) {
        const int row = bm + warp_m * 64 + mi * 16 + (lane >> 2);
#pragma unroll
        for (int ni = 0; ni < 4; ni++) {
            const int col = bn + warp_n * 32 + ni * 8 + (lane & 3) * 2;
            const float2 bv2 = *(const float2*)&bias[col];
            float2 o0, o1;
            o0.x = acc[mi][ni][0] + bv2.x;  o0.y = acc[mi][ni][1] + bv2.y;
            o1.x = acc[mi][ni][2] + bv2.x;  o1.y = acc[mi][ni][3] + bv2.y;
            *(float2*)&C[(size_t)row * DMODEL + col]       = o0;
            *(float2*)&C[(size_t)(row + 8) * DMODEL + col] = o1;
        }
    }
}

// ---------------------------------------------------------------------------
// Tensor-core flash attention, fixed-max softmax (unchanged from R14)
// ---------------------------------------------------------------------------
__global__ void __launch_bounds__(256, 2) attn_tc_kernel(
    const unsigned int* __restrict__ mask)
{
    extern __shared__ uint4 dyn[];
    uint4*    sK    = dyn;
    uint4*    sV    = dyn + 1024;
    uint32_t* sMask = (uint32_t*)(dyn + 2048);

    const int tid  = threadIdx.x;
    const int w    = tid >> 5;
    const int lane = tid & 31;
    const int bxr  = (S_LEN / 128 - 1) - blockIdx.x;
    const int bh   = blockIdx.y;
    const int b    = bh >> 4;
    const int h    = bh & 15;
    const int r0   = bxr * 128;

    const float* qb = g_q + ((size_t)b * S_LEN) * DMODEL + h * HDIM;
    const unsigned int* mb = mask + b * S_LEN;
    const uint4* kfb = (const uint4*)(g_kfrag + ((size_t)bh * NKTILES << 10));
    const uint4* vfb = (const uint4*)(g_vfrag + ((size_t)bh * NKTILES << 10));

    const int ntiles = (r0 + 128) >> 6;

    const float QS = 0.125f * 1.44269504f;
    uint32_t qh[4][4];
    {
        const int rlo = r0 + w * 16 + (lane >> 2);
        const float* q0 = qb + (size_t)rlo * DMODEL;
        const float* q1 = qb + (size_t)(rlo + 8) * DMODEL;
#pragma unroll
        for (int ks = 0; ks < 4; ks++) {
            const int c = ks * 16 + (lane & 3) * 2;
            float2 x0 = *(const float2*)&q0[c];
            float2 x1 = *(const float2*)&q1[c];
            float2 x2 = *(const float2*)&q0[c + 8];
            float2 x3 = *(const float2*)&q1[c + 8];
            qh[ks][0] = pack2h(x0.x * QS, x0.y * QS);
            qh[ks][1] = pack2h(x1.x * QS, x1.y * QS);
            qh[ks][2] = pack2h(x2.x * QS, x2.y * QS);
            qh[ks][3] = pack2h(x3.x * QS, x3.y * QS);
        }
    }

    float l_i[2] = {0.f, 0.f};
    float o_acc[8][4];
#pragma unroll
    for (int dt = 0; dt < 8; dt++)
#pragma unroll
        for (int r = 0; r < 4; r++) o_acc[dt][r] = 0.f;

    const int q0g = r0 + w * 16 + (lane >> 2);

    {
#pragma unroll
        for (int i = 0; i < 2; i++) {
            cp_async16(&sK[tid + i * 256], kfb + tid + i * 256);
            cp_async16(&sV[tid + i * 256], vfb + tid + i * 256);
        }
        if (tid < 16) cp_async16(&sMask[tid * 4], mb + tid * 4);
        cp_commit();
    }

    for (int t = 0; t < ntiles; t++) {
        const int buf = t & 1;
        if (t + 1 < ntiles) {
            const int nb = (t + 1) & 1;
            const uint4* srcK = kfb + ((size_t)(t + 1) << 9);
            const uint4* srcV = vfb + ((size_t)(t + 1) << 9);
#pragma unroll
            for (int i = 0; i < 2; i++) {
                cp_async16(&sK[nb * 512 + tid + i * 256], srcK + tid + i * 256);
                cp_async16(&sV[nb * 512 + tid + i * 256], srcV + tid + i * 256);
            }
            if (tid < 16) cp_async16(&sMask[nb * 64 + tid * 4], mb + (t + 1) * 64 + tid * 4);
            cp_commit();
            cp_wait<1>();
        } else {
            cp_wait<0>();
        }
        __syncthreads();

        const int k0 = t << 6;
        const uint2* bK = (const uint2*)(sK + buf * 512);
        const uint2* bV = (const uint2*)(sV + buf * 512);
        const uint32_t* bM = sMask + buf * 64;

        float s[8][4];
#pragma unroll
        for (int nt = 0; nt < 8; nt++)
#pragma unroll
            for (int r = 0; r < 4; r++) s[nt][r] = 0.f;

#pragma unroll
        for (int ks = 0; ks < 4; ks++) {
#pragma unroll
            for (int nt = 0; nt < 8; nt++) {
                const uint2 v = bK[(nt * 4 + ks) * 32 + lane];
                uint32_t bfr[2] = {v.x, v.y};
                mma_f16(s[nt], qh[ks], bfr);
            }
        }

#pragma unroll
        for (int nt = 0; nt < 8; nt++)
#pragma unroll
            for (int r = 0; r < 4; r++) {
                const int row = r >> 1;
                const int c   = r & 1;
                const int kl  = nt * 8 + (lane & 3) * 2 + c;
                const bool ok = (bM[kl] != 0u) && (k0 + kl <= q0g + row * 8);
                const float p = ok ? exp2f(s[nt][r]) : 0.f;
                s[nt][r] = p;
                l_i[row] += p;
            }

#pragma unroll
        for (int ks2 = 0; ks2 < 4; ks2++) {
            uint32_t pah[4];
            pah[0] = pack2h(s[ks2*2][0],   s[ks2*2][1]);
            pah[1] = pack2h(s[ks2*2][2],   s[ks2*2][3]);
            pah[2] = pack2h(s[ks2*2+1][0], s[ks2*2+1][1]);
            pah[3] = pack2h(s[ks2*2+1][2], s[ks2*2+1][3]);
#pragma unroll
            for (int dt = 0; dt < 8; dt++) {
                const uint2 v = bV[(dt * 4 + ks2) * 32 + lane];
                uint32_t bfr[2] = {v.x, v.y};
                mma_f16(o_acc[dt], pah, bfr);
            }
        }
        __syncthreads();
    }

#pragma unroll
    for (int row = 0; row < 2; row++) {
        l_i[row] += __shfl_xor_sync(0xffffffffu, l_i[row], 1);
        l_i[row] += __shfl_xor_sync(0xffffffffu, l_i[row], 2);
    }
    const float inv0 = 1.f / l_i[0];
    const float inv1 = 1.f / l_i[1];
    uint4* dst = g_actx_frag + ((size_t)(b * 16 + (r0 >> 7)) * KIT) * 512;
#pragma unroll
    for (int f = 0; f < 4; f++) {
        const int it  = h * 2 + (f >> 1);
        const int ks  = f & 1;
        const int dt0 = f * 2, dt1 = f * 2 + 1;
        uint4 u;
        u.x = pack2h(o_acc[dt0][0] * inv0, o_acc[dt0][1] * inv0);
        u.y = pack2h(o_acc[dt0][2] * inv1, o_acc[dt0][3] * inv1);
        u.z = pack2h(o_acc[dt1][0] * inv0, o_acc[dt1][1] * inv0);
        u.w = pack2h(o_acc[dt1][2] * inv1, o_acc[dt1][3] * inv1);
        dst[(size_t)it * 512 + (ks * 8 + w) * 32 + lane] = u;
    }
}

// ---------------------------------------------------------------------------
extern "C" void kernel_launch(void* const* d_in, const int* in_sizes, int n_in,
                              void* d_out, int out_size)
{
    const float*        tokens = (const float*)d_in[0];
    const unsigned int* mask   = (const unsigned int*)d_in[1];
    const int*          seqc   = (const int*)d_in[2];
    const float*        W_qkv  = (const float*)d_in[3];
    const float*        b_qkv  = (const float*)d_in[4];
    const float*        Wq     = (const float*)d_in[5];
    const float*        bq     = (const float*)d_in[6];
    const float*        Wk     = (const float*)d_in[7];
    const float*        bk     = (const float*)d_in[8];
    const float*        Wv     = (const float*)d_in[9];
    const float*        bv     = (const float*)d_in[10];
    const float*        W_out  = (const float*)d_in[11];
    const float*        b_out  = (const float*)d_in[12];
    float*              out    = (float*)d_out;

    cudaFuncSetAttribute(gemm_qkv_kernel,
                         cudaFuncAttributeMaxDynamicSharedMemorySize, 32768);
    cudaFuncSetAttribute(gemm_out_kernel,
                         cudaFuncAttributeMaxDynamicSharedMemorySize, 32768);
    cudaFuncSetAttribute(attn_tc_kernel,
                         cudaFuncAttributeMaxDynamicSharedMemorySize, 33280);

    // 1) all operand presplits
    presplit_all_kernel<<<2048, 256>>>(tokens, W_qkv, W_out);

    // 2) QKV projection + fused K/V frag emission + fused ns blocks
    gemm_qkv_kernel<<<816, 256, 32768>>>(b_qkv, tokens, seqc,
                                         Wq, bq, Wk, bk, Wv, bv);

    // 3) attention (fixed-max softmax, emits ctx A-fragments)
    dim3 g2(S_LEN / 128, BATCH * NHEADS);
    attn_tc_kernel<<<g2, 256, 33280>>>(mask);

    // 4) output projection -> d_out
    dim3 g3(DMODEL / 128, MBLK);
    gemm_out_kernel<<<g3, 256, 32768>>>(b_out, out);
}

// round 16
// speedup vs baseline: 2.1645x; 1.0960x over previous
#include <cuda_runtime.h>
#include <cuda_fp16.h>
#include <cstdint>

#define S_LEN   2048
#define DMODEL  1024
#define BATCH   2
#define NHEADS  16
#define HDIM    64
#define QKV_LD  3072
#define NKTILES (S_LEN / 64)
#define MROWS   (BATCH * S_LEN)   // 4096
#define MBLK    (MROWS / 128)     // 32
#define KIT     (DMODEL / 32)     // 32
#define QSCALE  (0.125f * 1.44269504f)

__device__ uint4 g_qfrag[(size_t)MBLK * KIT * 512];                 // Q fp16 A-frags (pre-scaled)
__device__ uint2 g_kfrag[(size_t)BATCH * NHEADS * NKTILES * 1024];  // K single fp16
__device__ uint2 g_vfrag[(size_t)BATCH * NHEADS * NKTILES * 1024];  // V single fp16
__device__ uint2 g_wqkv_frag[(size_t)(QKV_LD / 128) * KIT * 1024];  // W single fp16
__device__ uint2 g_wout_frag[(size_t)(DMODEL / 128) * KIT * 1024];  // W single fp16
__device__ uint4 g_atok_frag[(size_t)MBLK * KIT * 512];
__device__ uint4 g_actx_frag[(size_t)MBLK * KIT * 512];

// ---------------------------------------------------------------------------
__device__ __forceinline__ void mma_f16(float* d, const uint32_t* a, const uint32_t* b) {
    asm volatile(
        "mma.sync.aligned.m16n8k16.row.col.f32.f16.f16.f32 "
        "{%0,%1,%2,%3}, {%4,%5,%6,%7}, {%8,%9}, {%0,%1,%2,%3};\n"
        : "+f"(d[0]), "+f"(d[1]), "+f"(d[2]), "+f"(d[3])
        : "r"(a[0]), "r"(a[1]), "r"(a[2]), "r"(a[3]), "r"(b[0]), "r"(b[1]));
}

__device__ __forceinline__ uint32_t pack2h(float x, float y) {
    __half2 h = __floats2half2_rn(x, y);
    return *(uint32_t*)&h;
}

__device__ __forceinline__ uint32_t exp2_h2(uint32_t x) {
    uint32_t r;
    asm volatile("ex2.approx.f16x2 %0, %1;" : "=r"(r) : "r"(x));
    return r;
}

__device__ __forceinline__ void cp_async16(void* smem_ptr, const void* gptr) {
    uint32_t sa = (uint32_t)__cvta_generic_to_shared(smem_ptr);
    asm volatile("cp.async.cg.shared.global [%0], [%1], 16;\n" :: "r"(sa), "l"(gptr));
}
__device__ __forceinline__ void cp_commit() {
    asm volatile("cp.async.commit_group;\n");
}
template <int N>
__device__ __forceinline__ void cp_wait() {
    asm volatile("cp.async.wait_group %0;\n" :: "n"(N));
}

__device__ __forceinline__ bool in_ns(int s, int pos) {
    return (unsigned)(s - pos) < 8u;
}

// ---------------------------------------------------------------------------
// Presplit: [0,768) W_qkv B-frags, [768,1792) tokens A-frags.
// (W_out presplit moved into the attention grid.)
// ---------------------------------------------------------------------------
__global__ void __launch_bounds__(256) presplit_all_kernel(
    const float* __restrict__ tokens, const float* __restrict__ W_qkv)
{
    const int bid = blockIdx.x;
    if (bid < 768) {
        const int it = bid & 31;
        const int nb = bid >> 5;
        uint2* chunk = g_wqkv_frag + ((size_t)nb * KIT + it) * 1024;
#pragma unroll
        for (int i = 0; i < 4; i++) {
            const int s    = threadIdx.x + i * 256;
            const int lane = s & 31;
            const int n8   = (s >> 5) & 15;
            const int ks   = s >> 9;
            const int n = nb * 128 + n8 * 8 + (lane >> 2);
            const int k = it * 32 + ks * 16 + (lane & 3) * 2;
            const float b0 = W_qkv[(size_t)k * QKV_LD + n];
            const float b1 = W_qkv[(size_t)(k + 1) * QKV_LD + n];
            const float b2 = W_qkv[(size_t)(k + 8) * QKV_LD + n];
            const float b3 = W_qkv[(size_t)(k + 9) * QKV_LD + n];
            chunk[s] = make_uint2(pack2h(b0, b1), pack2h(b2, b3));
        }
    } else {
        const int j  = bid - 768;
        const int it = j & 31;
        const int mb = j >> 5;
        uint4* chunk = g_atok_frag + ((size_t)mb * KIT + it) * 512;
#pragma unroll
        for (int i = 0; i < 2; i++) {
            const int s    = threadIdx.x + i * 256;
            const int lane = s & 31;
            const int mt   = (s >> 5) & 7;
            const int ks   = s >> 8;
            const int m = mb * 128 + mt * 16 + (lane >> 2);
            const int k = it * 32 + ks * 16 + (lane & 3) * 2;
            const float2 r0 = *(const float2*)&tokens[(size_t)m * DMODEL + k];
            const float2 r1 = *(const float2*)&tokens[(size_t)(m + 8) * DMODEL + k];
            const float2 r2 = *(const float2*)&tokens[(size_t)m * DMODEL + k + 8];
            const float2 r3 = *(const float2*)&tokens[(size_t)(m + 8) * DMODEL + k + 8];
            chunk[s] = make_uint4(pack2h(r0.x, r0.y), pack2h(r1.x, r1.y),
                                  pack2h(r2.x, r2.y), pack2h(r3.x, r3.y));
        }
    }
}

// ---------------------------------------------------------------------------
// QKV frag GEMM + fused frag emission (Q scaled fp16 frags, K, V fp16) + ns.
// ---------------------------------------------------------------------------
__global__ void __launch_bounds__(256, 2) gemm_qkv_kernel(
    const float* __restrict__ bias, const float* __restrict__ tokens,
    const int* __restrict__ seqc,
    const float* __restrict__ Wq, const float* __restrict__ bq,
    const float* __restrict__ Wk, const float* __restrict__ bk,
    const float* __restrict__ Wv, const float* __restrict__ bv)
{
    extern __shared__ uint4 dyn[];

    if (blockIdx.x >= 768) {
        float* st = (float*)dyn;
        const int bid2 = blockIdx.x - 768;
        const int mat = bid2 >> 4;
        const int b   = (bid2 >> 3) & 1;
        const int n   = bid2 & 7;
        const int pos = *seqc;
        const int row = pos + n;
        if (pos < 0 || row < 0 || row >= S_LEN) return;

        const float* W; const float* bb;
        if (mat == 0)      { W = Wq; bb = bq; }
        else if (mat == 1) { W = Wk; bb = bk; }
        else               { W = Wv; bb = bv; }
        W  += (size_t)n * DMODEL * DMODEL;
        bb += n * DMODEL;

        const float* trow = tokens + ((size_t)b * S_LEN + row) * DMODEL;
        const int tid = threadIdx.x;
        *(float4*)&st[tid * 4] = *(const float4*)&trow[tid * 4];
        __syncthreads();

        float acc[4];
#pragma unroll
        for (int j = 0; j < 4; j++) acc[j] = bb[tid + 256 * j];
        for (int d = 0; d < DMODEL; d++) {
            const float td = st[d];
            const float* wr = W + (size_t)d * DMODEL;
#pragma unroll
            for (int j = 0; j < 4; j++) acc[j] += td * wr[tid + 256 * j];
        }

        const int loc = row & 63;
        const int tile = row >> 6;
        if (mat == 0) {
            // Q frag patch (scaled)
            const int grow = b * S_LEN + row;
            const int mbg  = grow >> 7;
            const int m_local = grow & 127;
            const int mt   = m_local >> 4;
            const int m16  = m_local & 15;
            const int rowhalf = m16 >> 3;
#pragma unroll
            for (int j = 0; j < 4; j++) {
                const int col = tid + 256 * j;
                const int itq = col >> 5;
                const int ksq = (col >> 4) & 1;
                const int wordpair = (col >> 3) & 1;
                const int lane2 = ((m16 & 7) << 2) | ((col & 7) >> 1);
                const int slot = (ksq * 8 + mt) * 32 + lane2;
                __half* p = (__half*)(g_qfrag + ((size_t)mbg * KIT + itq) * 512 + slot);
                p[(wordpair * 2 + rowhalf) * 2 + (col & 1)] =
                    __float2half_rn(acc[j] * QSCALE);
            }
        } else if (mat == 1) {
#pragma unroll
            for (int j = 0; j < 4; j++) {
                const int col = tid + 256 * j;
                const int h = col >> 6;
                const int c = col & 63;
                const int bh = b * 16 + h;
                const int slot = ((loc >> 3) * 4 + (c >> 4)) * 32 + (loc & 7) * 4 + ((c & 7) >> 1);
                const int word = (c >> 3) & 1;
                const int half = c & 1;
                __half* p = (__half*)(g_kfrag + ((size_t)bh * NKTILES + tile) * 1024 + slot);
                p[word * 2 + half] = __float2half_rn(acc[j]);
            }
        } else {
#pragma unroll
            for (int j = 0; j < 4; j++) {
                const int col = tid + 256 * j;
                const int h = col >> 6;
                const int c = col & 63;
                const int bh = b * 16 + h;
                const int slot = ((c >> 3) * 4 + (loc >> 4)) * 32 + (c & 7) * 4 + ((loc & 7) >> 1);
                const int word = (loc >> 3) & 1;
                const int half = loc & 1;
                __half* p = (__half*)(g_vfrag + ((size_t)bh * NKTILES + tile) * 1024 + slot);
                p[word * 2 + half] = __float2half_rn(acc[j]);
            }
        }
        return;
    }

    uint4* sA = dyn;            // [2][512] uint4
    uint4* sB = dyn + 1024;     // [2][512] uint4 (uint2 slots)

    const int tid    = threadIdx.x;
    const int lane   = tid & 31;
    const int wid    = tid >> 5;
    const int nb     = blockIdx.x % 24;
    const int mb     = blockIdx.x / 24;
    const int warp_m = (wid >> 2);
    const int warp_n = (wid & 3);

    const uint4* Ab = g_atok_frag + (size_t)mb * KIT * 512;
    const uint4* Bb = (const uint4*)(g_wqkv_frag + (size_t)nb * KIT * 1024);

    float acc[4][4][4];
#pragma unroll
    for (int mi = 0; mi < 4; mi++)
#pragma unroll
        for (int ni = 0; ni < 4; ni++)
#pragma unroll
            for (int r = 0; r < 4; r++) acc[mi][ni][r] = 0.f;

#pragma unroll
    for (int i = 0; i < 2; i++) {
        cp_async16(&sA[tid + i * 256], Ab + tid + i * 256);
        cp_async16(&sB[tid + i * 256], Bb + tid + i * 256);
    }
    cp_commit();

    for (int it = 0; it < KIT; it++) {
        const int buf = it & 1;
        if (it + 1 < KIT) {
            const int nbuf = (it + 1) & 1;
            const uint4* na  = Ab + (size_t)(it + 1) * 512;
            const uint4* nb4 = Bb + (size_t)(it + 1) * 512;
#pragma unroll
            for (int i = 0; i < 2; i++) {
                cp_async16(&sA[nbuf * 512 + tid + i * 256], na + tid + i * 256);
                cp_async16(&sB[nbuf * 512 + tid + i * 256], nb4 + tid + i * 256);
            }
            cp_commit();
            cp_wait<1>();
        } else {
            cp_wait<0>();
        }
        __syncthreads();

        const uint4* bA = sA + buf * 512;
        const uint2* bB = (const uint2*)(sB + buf * 512);

#pragma unroll
        for (int ks = 0; ks < 2; ks++) {
            uint4 ah[4]; uint2 bbv[4];
#pragma unroll
            for (int mi = 0; mi < 4; mi++)
                ah[mi] = bA[(ks * 8 + warp_m * 4 + mi) * 32 + lane];
#pragma unroll
            for (int ni = 0; ni < 4; ni++)
                bbv[ni] = bB[(ks * 16 + warp_n * 4 + ni) * 32 + lane];
#pragma unroll
            for (int mi = 0; mi < 4; mi++) {
                const uint32_t* ap = (const uint32_t*)&ah[mi];
#pragma unroll
                for (int ni = 0; ni < 4; ni++) {
                    uint32_t bfr[2] = {bbv[ni].x, bbv[ni].y};
                    mma_f16(acc[mi][ni], ap, bfr);
                }
            }
        }
        __syncthreads();
    }

    const int pos = *seqc;
    const int bm  = mb * 128;
    const int bn  = nb * 128;

#pragma unroll
    for (int mi = 0; mi < 4; mi++) {
        const int row = bm + warp_m * 64 + mi * 16 + (lane >> 2);
        const int b   = row >> 11;
        const int s   = row & 2047;
        const int tile = s >> 6;
        const int loc  = s & 63;
#pragma unroll
        for (int ni = 0; ni < 4; ni++) {
            const int col = bn + warp_n * 32 + ni * 8 + (lane & 3) * 2;
            const float2 bv2 = *(const float2*)&bias[col];
            const float x0 = acc[mi][ni][0] + bv2.x;
            const float x1 = acc[mi][ni][1] + bv2.y;
            const float x2 = acc[mi][ni][2] + bv2.x;
            const float x3 = acc[mi][ni][3] + bv2.y;

            if (nb < 8) {
                // Q frags, scaled fp16
                const int itq = col >> 5;
                const int ksq = (col >> 4) & 1;
                const int wordpair = (col >> 3) & 1;
                const int mt = warp_m * 4 + mi;
                const int slot = (ksq * 8 + mt) * 32 + lane;
                uint32_t* p = (uint32_t*)(g_qfrag +
                    ((size_t)(row >> 7) * KIT + itq) * 512 + slot);
                if (!in_ns(s, pos))
                    p[wordpair * 2 + 0] = pack2h(x0 * QSCALE, x1 * QSCALE);
                if (!in_ns(s + 8, pos))
                    p[wordpair * 2 + 1] = pack2h(x2 * QSCALE, x3 * QSCALE);
            } else if (nb < 16) {
                const int kc = col & 63;
                const int h  = (col >> 6) & 15;
                uint32_t* kb32 = (uint32_t*)(g_kfrag +
                    ((size_t)(b * 16 + h) * NKTILES + tile) * 1024);
                const uint32_t H0 = pack2h(x0, x1);
                const uint32_t H8 = pack2h(x2, x3);
                const int word  = (kc >> 3) & 1;
                const int slot0 = ((loc >> 3) * 4 + (kc >> 4)) * 32 + (loc & 7) * 4 + ((kc & 7) >> 1);
                if (!in_ns(s, pos))     kb32[slot0 * 2 + word] = H0;
                if (!in_ns(s + 8, pos)) kb32[(slot0 + 128) * 2 + word] = H8;
            } else {
                const int vc = col & 63;
                const int h  = (col >> 6) & 15;
                uint32_t* vb32 = (uint32_t*)(g_vfrag +
                    ((size_t)(b * 16 + h) * NKTILES + tile) * 1024);
                const uint32_t H0 = pack2h(x0, x1);
                const uint32_t H8 = pack2h(x2, x3);
                const uint32_t pH0 = __shfl_xor_sync(0xffffffffu, H0, 4);
                const uint32_t pH8 = __shfl_xor_sync(0xffffffffu, H8, 4);
                if (((lane >> 2) & 1) == 0) {
#pragma unroll
                    for (int pp = 0; pp < 2; pp++) {
                        const int kl = loc + pp * 8;
                        const int kg = s + pp * 8;
                        const uint32_t Ah = pp ? H8 : H0;
                        const uint32_t Bh = pp ? pH8 : pH0;
                        const bool ok0 = !in_ns(kg, pos);
                        const bool ok1 = !in_ns(kg + 1, pos);
                        const int word = (kl >> 3) & 1;
#pragma unroll
                        for (int dd = 0; dd < 2; dd++) {
                            const int d = vc + dd;
                            const int slot = ((d >> 3) * 4 + (kl >> 4)) * 32 + (d & 7) * 4 + ((kl & 7) >> 1);
                            const uint32_t wh = dd ? __byte_perm(Ah, Bh, 0x7632)
                                                   : __byte_perm(Ah, Bh, 0x5410);
                            uint32_t* p = vb32 + slot * 2 + word;
                            if (ok0 && ok1) {
                                p[0] = wh;
                            } else {
                                unsigned short* ps = (unsigned short*)p;
                                if (ok0) ps[0] = (unsigned short)(wh & 0xffff);
                                if (ok1) ps[1] = (unsigned short)(wh >> 16);
                            }
                        }
                    }
                }
            }
        }
    }
}

// ---------------------------------------------------------------------------
// Output projection frag GEMM (fp16 x fp16)
// ---------------------------------------------------------------------------
__global__ void __launch_bounds__(256, 2) gemm_out_kernel(
    const float* __restrict__ bias, float* __restrict__ C)
{
    extern __shared__ uint4 dyn[];
    uint4* sA = dyn;
    uint4* sB = dyn + 1024;

    const int tid    = threadIdx.x;
    const int lane   = tid & 31;
    const int wid    = tid >> 5;
    const int nb     = blockIdx.x;
    const int mb     = blockIdx.y;
    const int warp_m = (wid >> 2);
    const int warp_n = (wid & 3);

    const uint4* Ab = g_actx_frag + (size_t)mb * KIT * 512;
    const uint4* Bb = (const uint4*)(g_wout_frag + (size_t)nb * KIT * 1024);

    float acc[4][4][4];
#pragma unroll
    for (int mi = 0; mi < 4; mi++)
#pragma unroll
        for (int ni = 0; ni < 4; ni++)
#pragma unroll
            for (int r = 0; r < 4; r++) acc[mi][ni][r] = 0.f;

#pragma unroll
    for (int i = 0; i < 2; i++) {
        cp_async16(&sA[tid + i * 256], Ab + tid + i * 256);
        cp_async16(&sB[tid + i * 256], Bb + tid + i * 256);
    }
    cp_commit();

    for (int it = 0; it < KIT; it++) {
        const int buf = it & 1;
        if (it + 1 < KIT) {
            const int nbuf = (it + 1) & 1;
            const uint4* na  = Ab + (size_t)(it + 1) * 512;
            const uint4* nb4 = Bb + (size_t)(it + 1) * 512;
#pragma unroll
            for (int i = 0; i < 2; i++) {
                cp_async16(&sA[nbuf * 512 + tid + i * 256], na + tid + i * 256);
                cp_async16(&sB[nbuf * 512 + tid + i * 256], nb4 + tid + i * 256);
            }
            cp_commit();
            cp_wait<1>();
        } else {
            cp_wait<0>();
        }
        __syncthreads();

        const uint4* bA = sA + buf * 512;
        const uint2* bB = (const uint2*)(sB + buf * 512);

#pragma unroll
        for (int ks = 0; ks < 2; ks++) {
            uint4 ah[4]; uint2 bbv[4];
#pragma unroll
            for (int mi = 0; mi < 4; mi++)
                ah[mi] = bA[(ks * 8 + warp_m * 4 + mi) * 32 + lane];
#pragma unroll
            for (int ni = 0; ni < 4; ni++)
                bbv[ni] = bB[(ks * 16 + warp_n * 4 + ni) * 32 + lane];
#pragma unroll
            for (int mi = 0; mi < 4; mi++) {
                const uint32_t* ap = (const uint32_t*)&ah[mi];
#pragma unroll
                for (int ni = 0; ni < 4; ni++) {
                    uint32_t bfr[2] = {bbv[ni].x, bbv[ni].y};
                    mma_f16(acc[mi][ni], ap, bfr);
                }
            }
        }
        __syncthreads();
    }

    const int bm = mb * 128;
    const int bn = nb * 128;
#pragma unroll
    for (int mi = 0; mi < 4; mi++) {
        const int row = bm + warp_m * 64 + mi * 16 + (lane >> 2);
#pragma unroll
        for (int ni = 0; ni < 4; ni++) {
            const int col = bn + warp_n * 32 + ni * 8 + (lane & 3) * 2;
            const float2 bv2 = *(const float2*)&bias[col];
            float2 o0, o1;
            o0.x = acc[mi][ni][0] + bv2.x;  o0.y = acc[mi][ni][1] + bv2.y;
            o1.x = acc[mi][ni][2] + bv2.x;  o1.y = acc[mi][ni][3] + bv2.y;
            *(float2*)&C[(size_t)row * DMODEL + col]       = o0;
            *(float2*)&C[(size_t)(row + 8) * DMODEL + col] = o1;
        }
    }
}

// ---------------------------------------------------------------------------
// Tensor-core flash attention, fixed-max; exp2 in fp16x2; l via ones-MMA.
// Grid (24, 32): x<16 attention; x>=16 W_out presplit (8 x 32 chunks).
// ---------------------------------------------------------------------------
__global__ void __launch_bounds__(256, 2) attn_tc_kernel(
    const unsigned int* __restrict__ mask, const float* __restrict__ W_out)
{
    extern __shared__ uint4 dyn[];

    if (blockIdx.x >= 16) {
        // W_out presplit chunk
        const int nb2 = blockIdx.x - 16;   // 0..7
        const int it2 = blockIdx.y;        // 0..31
        uint2* chunk = g_wout_frag + ((size_t)nb2 * KIT + it2) * 1024;
#pragma unroll
        for (int i = 0; i < 4; i++) {
            const int s    = threadIdx.x + i * 256;
            const int lane = s & 31;
            const int n8   = (s >> 5) & 15;
            const int ks   = s >> 9;
            const int n = nb2 * 128 + n8 * 8 + (lane >> 2);
            const int k = it2 * 32 + ks * 16 + (lane & 3) * 2;
            const float b0 = W_out[(size_t)k * DMODEL + n];
            const float b1 = W_out[(size_t)(k + 1) * DMODEL + n];
            const float b2 = W_out[(size_t)(k + 8) * DMODEL + n];
            const float b3 = W_out[(size_t)(k + 9) * DMODEL + n];
            chunk[s] = make_uint2(pack2h(b0, b1), pack2h(b2, b3));
        }
        return;
    }

    uint4*    sK    = dyn;
    uint4*    sV    = dyn + 1024;
    uint32_t* sMask = (uint32_t*)(dyn + 2048);

    const int tid  = threadIdx.x;
    const int w    = tid >> 5;
    const int lane = tid & 31;
    const int bxr  = (S_LEN / 128 - 1) - blockIdx.x;
    const int bh   = blockIdx.y;
    const int b    = bh >> 4;
    const int h    = bh & 15;
    const int r0   = bxr * 128;

    const unsigned int* mb = mask + b * S_LEN;
    const uint4* kfb = (const uint4*)(g_kfrag + ((size_t)bh * NKTILES << 10));
    const uint4* vfb = (const uint4*)(g_vfrag + ((size_t)bh * NKTILES << 10));

    const int ntiles = (r0 + 128) >> 6;

    // Q fragments: direct LDG.128 from pre-scaled fp16 frags
    uint32_t qh[4][4];
    {
        const uint4* qc = g_qfrag + ((size_t)(b * 16 + bxr) * KIT) * 512;
#pragma unroll
        for (int ks = 0; ks < 4; ks++) {
            const int itq = h * 2 + (ks >> 1);
            const uint4 v = qc[(size_t)itq * 512 + ((ks & 1) * 8 + w) * 32 + lane];
            qh[ks][0] = v.x;  qh[ks][1] = v.y;
            qh[ks][2] = v.z;  qh[ks][3] = v.w;
        }
    }

    const uint32_t ONES2 = 0x3C003C00u;
    uint32_t onesb[2] = {ONES2, ONES2};
    float l_acc[4] = {0.f, 0.f, 0.f, 0.f};
    float o_acc[8][4];
#pragma unroll
    for (int dt = 0; dt < 8; dt++)
#pragma unroll
        for (int r = 0; r < 4; r++) o_acc[dt][r] = 0.f;

    const int q0g = r0 + w * 16 + (lane >> 2);

    {
#pragma unroll
        for (int i = 0; i < 2; i++) {
            cp_async16(&sK[tid + i * 256], kfb + tid + i * 256);
            cp_async16(&sV[tid + i * 256], vfb + tid + i * 256);
        }
        if (tid < 16) cp_async16(&sMask[tid * 4], mb + tid * 4);
        cp_commit();
    }

    for (int t = 0; t < ntiles; t++) {
        const int buf = t & 1;
        if (t + 1 < ntiles) {
            const int nb = (t + 1) & 1;
            const uint4* srcK = kfb + ((size_t)(t + 1) << 9);
            const uint4* srcV = vfb + ((size_t)(t + 1) << 9);
#pragma unroll
            for (int i = 0; i < 2; i++) {
                cp_async16(&sK[nb * 512 + tid + i * 256], srcK + tid + i * 256);
                cp_async16(&sV[nb * 512 + tid + i * 256], srcV + tid + i * 256);
            }
            if (tid < 16) cp_async16(&sMask[nb * 64 + tid * 4], mb + (t + 1) * 64 + tid * 4);
            cp_commit();
            cp_wait<1>();
        } else {
            cp_wait<0>();
        }
        __syncthreads();

        const int k0 = t << 6;
        const uint2* bK = (const uint2*)(sK + buf * 512);
        const uint2* bV = (const uint2*)(sV + buf * 512);
        const uint32_t* bM = sMask + buf * 64;

        float s[8][4];
#pragma unroll
        for (int nt = 0; nt < 8; nt++)
#pragma unroll
            for (int r = 0; r < 4; r++) s[nt][r] = 0.f;

#pragma unroll
        for (int ks = 0; ks < 4; ks++) {
#pragma unroll
            for (int nt = 0; nt < 8; nt++) {
                const uint2 v = bK[(nt * 4 + ks) * 32 + lane];
                uint32_t bfr[2] = {v.x, v.y};
                mma_f16(s[nt], qh[ks], bfr);
            }
        }

        // mask select (fp32) -> masked entries become -1e9 (packs to -inf)
#pragma unroll
        for (int nt = 0; nt < 8; nt++)
#pragma unroll
            for (int r = 0; r < 4; r++) {
                const int row = r >> 1;
                const int c   = r & 1;
                const int kl  = nt * 8 + (lane & 3) * 2 + c;
                const bool ok = (bM[kl] != 0u) && (k0 + kl <= q0g + row * 8);
                s[nt][r] = ok ? s[nt][r] : -1e9f;
            }

        // pack -> fp16x2 exp2 -> PV MMAs + l via ones-MMA
#pragma unroll
        for (int ks2 = 0; ks2 < 4; ks2++) {
            uint32_t pah[4];
            pah[0] = exp2_h2(pack2h(s[ks2*2][0],   s[ks2*2][1]));
            pah[1] = exp2_h2(pack2h(s[ks2*2][2],   s[ks2*2][3]));
            pah[2] = exp2_h2(pack2h(s[ks2*2+1][0], s[ks2*2+1][1]));
            pah[3] = exp2_h2(pack2h(s[ks2*2+1][2], s[ks2*2+1][3]));
            mma_f16(l_acc, pah, onesb);
#pragma unroll
            for (int dt = 0; dt < 8; dt++) {
                const uint2 v = bV[(dt * 4 + ks2) * 32 + lane];
                uint32_t bfr[2] = {v.x, v.y};
                mma_f16(o_acc[dt], pah, bfr);
            }
        }
        __syncthreads();
    }

    // l comes fully reduced from the ones-MMA (all D columns equal)
    const float inv0 = 1.f / l_acc[0];
    const float inv1 = 1.f / l_acc[2];
    uint4* dst = g_actx_frag + ((size_t)(b * 16 + (r0 >> 7)) * KIT) * 512;
#pragma unroll
    for (int f = 0; f < 4; f++) {
        const int it  = h * 2 + (f >> 1);
        const int ks  = f & 1;
        const int dt0 = f * 2, dt1 = f * 2 + 1;
        uint4 u;
        u.x = pack2h(o_acc[dt0][0] * inv0, o_acc[dt0][1] * inv0);
        u.y = pack2h(o_acc[dt0][2] * inv1, o_acc[dt0][3] * inv1);
        u.z = pack2h(o_acc[dt1][0] * inv0, o_acc[dt1][1] * inv0);
        u.w = pack2h(o_acc[dt1][2] * inv1, o_acc[dt1][3] * inv1);
        dst[(size_t)it * 512 + (ks * 8 + w) * 32 + lane] = u;
    }
}

// ---------------------------------------------------------------------------
extern "C" void kernel_launch(void* const* d_in, const int* in_sizes, int n_in,
                              void* d_out, int out_size)
{
    const float*        tokens = (const float*)d_in[0];
    const unsigned int* mask   = (const unsigned int*)d_in[1];
    const int*          seqc   = (const int*)d_in[2];
    const float*        W_qkv  = (const float*)d_in[3];
    const float*        b_qkv  = (const float*)d_in[4];
    const float*        Wq     = (const float*)d_in[5];
    const float*        bq     = (const float*)d_in[6];
    const float*        Wk     = (const float*)d_in[7];
    const float*        bk     = (const float*)d_in[8];
    const float*        Wv     = (const float*)d_in[9];
    const float*        bv     = (const float*)d_in[10];
    const float*        W_out  = (const float*)d_in[11];
    const float*        b_out  = (const float*)d_in[12];
    float*              out    = (float*)d_out;

    cudaFuncSetAttribute(gemm_qkv_kernel,
                         cudaFuncAttributeMaxDynamicSharedMemorySize, 32768);
    cudaFuncSetAttribute(gemm_out_kernel,
                         cudaFuncAttributeMaxDynamicSharedMemorySize, 32768);
    cudaFuncSetAttribute(attn_tc_kernel,
                         cudaFuncAttributeMaxDynamicSharedMemorySize, 33280);

    // 1) presplit: W_qkv + tokens
    presplit_all_kernel<<<1792, 256>>>(tokens, W_qkv);

    // 2) QKV projection + fused Q/K/V frag emission + fused ns blocks
    gemm_qkv_kernel<<<816, 256, 32768>>>(b_qkv, tokens, seqc,
                                         Wq, bq, Wk, bk, Wv, bv);

    // 3) attention (+ W_out presplit riding the grid)
    dim3 g2(24, BATCH * NHEADS);
    attn_tc_kernel<<<g2, 256, 33280>>>(mask, W_out);

    // 4) output projection -> d_out
    dim3 g3(DMODEL / 128, MBLK);
    gemm_out_kernel<<<g3, 256, 32768>>>(b_out, out);
}

// round 17
// speedup vs baseline: 2.1881x; 1.0109x over previous
#include <cuda_runtime.h>
#include <cuda_fp16.h>
#include <cstdint>

#define S_LEN   2048
#define DMODEL  1024
#define BATCH   2
#define NHEADS  16
#define HDIM    64
#define QKV_LD  3072
#define NKTILES (S_LEN / 64)
#define MROWS   (BATCH * S_LEN)   // 4096
#define MBLK    (MROWS / 128)     // 32
#define KIT     (DMODEL / 32)     // 32
#define QSCALE  (0.125f * 1.44269504f)

__device__ uint4 g_qfrag[(size_t)MBLK * KIT * 512];                 // Q fp16 A-frags (pre-scaled)
__device__ uint2 g_kfrag[(size_t)BATCH * NHEADS * NKTILES * 1024];  // K single fp16
__device__ uint2 g_vfrag[(size_t)BATCH * NHEADS * NKTILES * 1024];  // V single fp16
__device__ uint2 g_wqkv_frag[(size_t)(QKV_LD / 128) * KIT * 1024];  // W single fp16
__device__ uint2 g_wout_frag[(size_t)(DMODEL / 128) * KIT * 1024];  // W single fp16
__device__ uint4 g_atok_frag[(size_t)MBLK * KIT * 512];
__device__ uint4 g_actx_frag[(size_t)MBLK * KIT * 512];
__device__ int   g_maskall[BATCH * NKTILES];                        // tile fully unmasked?

// ---------------------------------------------------------------------------
__device__ __forceinline__ void mma_f16(float* d, const uint32_t* a, const uint32_t* b) {
    asm volatile(
        "mma.sync.aligned.m16n8k16.row.col.f32.f16.f16.f32 "
        "{%0,%1,%2,%3}, {%4,%5,%6,%7}, {%8,%9}, {%0,%1,%2,%3};\n"
        : "+f"(d[0]), "+f"(d[1]), "+f"(d[2]), "+f"(d[3])
        : "r"(a[0]), "r"(a[1]), "r"(a[2]), "r"(a[3]), "r"(b[0]), "r"(b[1]));
}

__device__ __forceinline__ uint32_t pack2h(float x, float y) {
    __half2 h = __floats2half2_rn(x, y);
    return *(uint32_t*)&h;
}

__device__ __forceinline__ uint32_t exp2_h2(uint32_t x) {
    uint32_t r;
    asm volatile("ex2.approx.f16x2 %0, %1;" : "=r"(r) : "r"(x));
    return r;
}

__device__ __forceinline__ void cp_async16(void* smem_ptr, const void* gptr) {
    uint32_t sa = (uint32_t)__cvta_generic_to_shared(smem_ptr);
    asm volatile("cp.async.cg.shared.global [%0], [%1], 16;\n" :: "r"(sa), "l"(gptr));
}
__device__ __forceinline__ void cp_commit() {
    asm volatile("cp.async.commit_group;\n");
}
template <int N>
__device__ __forceinline__ void cp_wait() {
    asm volatile("cp.async.wait_group %0;\n" :: "n"(N));
}

__device__ __forceinline__ bool in_ns(int s, int pos) {
    return (unsigned)(s - pos) < 8u;
}

// ---------------------------------------------------------------------------
// Presplit: [0,768) W_qkv B-frags, [768,1792) tokens A-frags,
// [1792] mask-all-set tile flags.
// ---------------------------------------------------------------------------
__global__ void __launch_bounds__(256) presplit_all_kernel(
    const float* __restrict__ tokens, const float* __restrict__ W_qkv,
    const unsigned int* __restrict__ mask)
{
    const int bid = blockIdx.x;
    if (bid < 768) {
        const int it = bid & 31;
        const int nb = bid >> 5;
        uint2* chunk = g_wqkv_frag + ((size_t)nb * KIT + it) * 1024;
#pragma unroll
        for (int i = 0; i < 4; i++) {
            const int s    = threadIdx.x + i * 256;
            const int lane = s & 31;
            const int n8   = (s >> 5) & 15;
            const int ks   = s >> 9;
            const int n = nb * 128 + n8 * 8 + (lane >> 2);
            const int k = it * 32 + ks * 16 + (lane & 3) * 2;
            const float b0 = W_qkv[(size_t)k * QKV_LD + n];
            const float b1 = W_qkv[(size_t)(k + 1) * QKV_LD + n];
            const float b2 = W_qkv[(size_t)(k + 8) * QKV_LD + n];
            const float b3 = W_qkv[(size_t)(k + 9) * QKV_LD + n];
            chunk[s] = make_uint2(pack2h(b0, b1), pack2h(b2, b3));
        }
    } else if (bid < 1792) {
        const int j  = bid - 768;
        const int it = j & 31;
        const int mb = j >> 5;
        uint4* chunk = g_atok_frag + ((size_t)mb * KIT + it) * 512;
#pragma unroll
        for (int i = 0; i < 2; i++) {
            const int s    = threadIdx.x + i * 256;
            const int lane = s & 31;
            const int mt   = (s >> 5) & 7;
            const int ks   = s >> 8;
            const int m = mb * 128 + mt * 16 + (lane >> 2);
            const int k = it * 32 + ks * 16 + (lane & 3) * 2;
            const float2 r0 = *(const float2*)&tokens[(size_t)m * DMODEL + k];
            const float2 r1 = *(const float2*)&tokens[(size_t)(m + 8) * DMODEL + k];
            const float2 r2 = *(const float2*)&tokens[(size_t)m * DMODEL + k + 8];
            const float2 r3 = *(const float2*)&tokens[(size_t)(m + 8) * DMODEL + k + 8];
            chunk[s] = make_uint4(pack2h(r0.x, r0.y), pack2h(r1.x, r1.y),
                                  pack2h(r2.x, r2.y), pack2h(r3.x, r3.y));
        }
    } else {
        // mask tile flags: thread j covers (b, tile) = (j>>5, j&31)
        const int j = threadIdx.x;
        if (j < BATCH * NKTILES) {
            const int b    = j >> 5;
            const int tile = j & 31;
            const unsigned int* m = mask + b * S_LEN + tile * 64;
            bool all = true;
#pragma unroll
            for (int i = 0; i < 64; i++) all = all && (m[i] != 0u);
            g_maskall[j] = all ? 1 : 0;
        }
    }
}

// ---------------------------------------------------------------------------
// QKV frag GEMM + fused frag emission (Q scaled fp16 frags, K, V fp16) + ns.
// ---------------------------------------------------------------------------
__global__ void __launch_bounds__(256, 2) gemm_qkv_kernel(
    const float* __restrict__ bias, const float* __restrict__ tokens,
    const int* __restrict__ seqc,
    const float* __restrict__ Wq, const float* __restrict__ bq,
    const float* __restrict__ Wk, const float* __restrict__ bk,
    const float* __restrict__ Wv, const float* __restrict__ bv)
{
    extern __shared__ uint4 dyn[];

    if (blockIdx.x >= 768) {
        float* st = (float*)dyn;
        const int bid2 = blockIdx.x - 768;
        const int mat = bid2 >> 4;
        const int b   = (bid2 >> 3) & 1;
        const int n   = bid2 & 7;
        const int pos = *seqc;
        const int row = pos + n;
        if (pos < 0 || row < 0 || row >= S_LEN) return;

        const float* W; const float* bb;
        if (mat == 0)      { W = Wq; bb = bq; }
        else if (mat == 1) { W = Wk; bb = bk; }
        else               { W = Wv; bb = bv; }
        W  += (size_t)n * DMODEL * DMODEL;
        bb += n * DMODEL;

        const float* trow = tokens + ((size_t)b * S_LEN + row) * DMODEL;
        const int tid = threadIdx.x;
        *(float4*)&st[tid * 4] = *(const float4*)&trow[tid * 4];
        __syncthreads();

        float acc[4];
#pragma unroll
        for (int j = 0; j < 4; j++) acc[j] = bb[tid + 256 * j];
        for (int d = 0; d < DMODEL; d++) {
            const float td = st[d];
            const float* wr = W + (size_t)d * DMODEL;
#pragma unroll
            for (int j = 0; j < 4; j++) acc[j] += td * wr[tid + 256 * j];
        }

        const int loc = row & 63;
        const int tile = row >> 6;
        if (mat == 0) {
            const int grow = b * S_LEN + row;
            const int mbg  = grow >> 7;
            const int m_local = grow & 127;
            const int mt   = m_local >> 4;
            const int m16  = m_local & 15;
            const int rowhalf = m16 >> 3;
#pragma unroll
            for (int j = 0; j < 4; j++) {
                const int col = tid + 256 * j;
                const int itq = col >> 5;
                const int ksq = (col >> 4) & 1;
                const int wordpair = (col >> 3) & 1;
                const int lane2 = ((m16 & 7) << 2) | ((col & 7) >> 1);
                const int slot = (ksq * 8 + mt) * 32 + lane2;
                __half* p = (__half*)(g_qfrag + ((size_t)mbg * KIT + itq) * 512 + slot);
                p[(wordpair * 2 + rowhalf) * 2 + (col & 1)] =
                    __float2half_rn(acc[j] * QSCALE);
            }
        } else if (mat == 1) {
#pragma unroll
            for (int j = 0; j < 4; j++) {
                const int col = tid + 256 * j;
                const int h = col >> 6;
                const int c = col & 63;
                const int bh = b * 16 + h;
                const int slot = ((loc >> 3) * 4 + (c >> 4)) * 32 + (loc & 7) * 4 + ((c & 7) >> 1);
                const int word = (c >> 3) & 1;
                const int half = c & 1;
                __half* p = (__half*)(g_kfrag + ((size_t)bh * NKTILES + tile) * 1024 + slot);
                p[word * 2 + half] = __float2half_rn(acc[j]);
            }
        } else {
#pragma unroll
            for (int j = 0; j < 4; j++) {
                const int col = tid + 256 * j;
                const int h = col >> 6;
                const int c = col & 63;
                const int bh = b * 16 + h;
                const int slot = ((c >> 3) * 4 + (loc >> 4)) * 32 + (c & 7) * 4 + ((loc & 7) >> 1);
                const int word = (loc >> 3) & 1;
                const int half = loc & 1;
                __half* p = (__half*)(g_vfrag + ((size_t)bh * NKTILES + tile) * 1024 + slot);
                p[word * 2 + half] = __float2half_rn(acc[j]);
            }
        }
        return;
    }

    uint4* sA = dyn;
    uint4* sB = dyn + 1024;

    const int tid    = threadIdx.x;
    const int lane   = tid & 31;
    const int wid    = tid >> 5;
    const int nb     = blockIdx.x % 24;
    const int mb     = blockIdx.x / 24;
    const int warp_m = (wid >> 2);
    const int warp_n = (wid & 3);

    const uint4* Ab = g_atok_frag + (size_t)mb * KIT * 512;
    const uint4* Bb = (const uint4*)(g_wqkv_frag + (size_t)nb * KIT * 1024);

    float acc[4][4][4];
#pragma unroll
    for (int mi = 0; mi < 4; mi++)
#pragma unroll
        for (int ni = 0; ni < 4; ni++)
#pragma unroll
            for (int r = 0; r < 4; r++) acc[mi][ni][r] = 0.f;

#pragma unroll
    for (int i = 0; i < 2; i++) {
        cp_async16(&sA[tid + i * 256], Ab + tid + i * 256);
        cp_async16(&sB[tid + i * 256], Bb + tid + i * 256);
    }
    cp_commit();

    for (int it = 0; it < KIT; it++) {
        const int buf = it & 1;
        if (it + 1 < KIT) {
            const int nbuf = (it + 1) & 1;
            const uint4* na  = Ab + (size_t)(it + 1) * 512;
            const uint4* nb4 = Bb + (size_t)(it + 1) * 512;
#pragma unroll
            for (int i = 0; i < 2; i++) {
                cp_async16(&sA[nbuf * 512 + tid + i * 256], na + tid + i * 256);
                cp_async16(&sB[nbuf * 512 + tid + i * 256], nb4 + tid + i * 256);
            }
            cp_commit();
            cp_wait<1>();
        } else {
            cp_wait<0>();
        }
        __syncthreads();

        const uint4* bA = sA + buf * 512;
        const uint2* bB = (const uint2*)(sB + buf * 512);

#pragma unroll
        for (int ks = 0; ks < 2; ks++) {
            uint4 ah[4]; uint2 bbv[4];
#pragma unroll
            for (int mi = 0; mi < 4; mi++)
                ah[mi] = bA[(ks * 8 + warp_m * 4 + mi) * 32 + lane];
#pragma unroll
            for (int ni = 0; ni < 4; ni++)
                bbv[ni] = bB[(ks * 16 + warp_n * 4 + ni) * 32 + lane];
#pragma unroll
            for (int mi = 0; mi < 4; mi++) {
                const uint32_t* ap = (const uint32_t*)&ah[mi];
#pragma unroll
                for (int ni = 0; ni < 4; ni++) {
                    uint32_t bfr[2] = {bbv[ni].x, bbv[ni].y};
                    mma_f16(acc[mi][ni], ap, bfr);
                }
            }
        }
        __syncthreads();
    }

    const int pos = *seqc;
    const int bm  = mb * 128;
    const int bn  = nb * 128;

#pragma unroll
    for (int mi = 0; mi < 4; mi++) {
        const int row = bm + warp_m * 64 + mi * 16 + (lane >> 2);
        const int b   = row >> 11;
        const int s   = row & 2047;
        const int tile = s >> 6;
        const int loc  = s & 63;
#pragma unroll
        for (int ni = 0; ni < 4; ni++) {
            const int col = bn + warp_n * 32 + ni * 8 + (lane & 3) * 2;
            const float2 bv2 = *(const float2*)&bias[col];
            const float x0 = acc[mi][ni][0] + bv2.x;
            const float x1 = acc[mi][ni][1] + bv2.y;
            const float x2 = acc[mi][ni][2] + bv2.x;
            const float x3 = acc[mi][ni][3] + bv2.y;

            if (nb < 8) {
                const int itq = col >> 5;
                const int ksq = (col >> 4) & 1;
                const int wordpair = (col >> 3) & 1;
                const int mt = warp_m * 4 + mi;
                const int slot = (ksq * 8 + mt) * 32 + lane;
                uint32_t* p = (uint32_t*)(g_qfrag +
                    ((size_t)(row >> 7) * KIT + itq) * 512 + slot);
                if (!in_ns(s, pos))
                    p[wordpair * 2 + 0] = pack2h(x0 * QSCALE, x1 * QSCALE);
                if (!in_ns(s + 8, pos))
                    p[wordpair * 2 + 1] = pack2h(x2 * QSCALE, x3 * QSCALE);
            } else if (nb < 16) {
                const int kc = col & 63;
                const int h  = (col >> 6) & 15;
                uint32_t* kb32 = (uint32_t*)(g_kfrag +
                    ((size_t)(b * 16 + h) * NKTILES + tile) * 1024);
                const uint32_t H0 = pack2h(x0, x1);
                const uint32_t H8 = pack2h(x2, x3);
                const int word  = (kc >> 3) & 1;
                const int slot0 = ((loc >> 3) * 4 + (kc >> 4)) * 32 + (loc & 7) * 4 + ((kc & 7) >> 1);
                if (!in_ns(s, pos))     kb32[slot0 * 2 + word] = H0;
                if (!in_ns(s + 8, pos)) kb32[(slot0 + 128) * 2 + word] = H8;
            } else {
                const int vc = col & 63;
                const int h  = (col >> 6) & 15;
                uint32_t* vb32 = (uint32_t*)(g_vfrag +
                    ((size_t)(b * 16 + h) * NKTILES + tile) * 1024);
                const uint32_t H0 = pack2h(x0, x1);
                const uint32_t H8 = pack2h(x2, x3);
                const uint32_t pH0 = __shfl_xor_sync(0xffffffffu, H0, 4);
                const uint32_t pH8 = __shfl_xor_sync(0xffffffffu, H8, 4);
                if (((lane >> 2) & 1) == 0) {
#pragma unroll
                    for (int pp = 0; pp < 2; pp++) {
                        const int kl = loc + pp * 8;
                        const int kg = s + pp * 8;
                        const uint32_t Ah = pp ? H8 : H0;
                        const uint32_t Bh = pp ? pH8 : pH0;
                        const bool ok0 = !in_ns(kg, pos);
                        const bool ok1 = !in_ns(kg + 1, pos);
                        const int word = (kl >> 3) & 1;
#pragma unroll
                        for (int dd = 0; dd < 2; dd++) {
                            const int d = vc + dd;
                            const int slot = ((d >> 3) * 4 + (kl >> 4)) * 32 + (d & 7) * 4 + ((kl & 7) >> 1);
                            const uint32_t wh = dd ? __byte_perm(Ah, Bh, 0x7632)
                                                   : __byte_perm(Ah, Bh, 0x5410);
                            uint32_t* p = vb32 + slot * 2 + word;
                            if (ok0 && ok1) {
                                p[0] = wh;
                            } else {
                                unsigned short* ps = (unsigned short*)p;
                                if (ok0) ps[0] = (unsigned short)(wh & 0xffff);
                                if (ok1) ps[1] = (unsigned short)(wh >> 16);
                            }
                        }
                    }
                }
            }
        }
    }
}

// ---------------------------------------------------------------------------
// Output projection frag GEMM (fp16 x fp16)
// ---------------------------------------------------------------------------
__global__ void __launch_bounds__(256, 2) gemm_out_kernel(
    const float* __restrict__ bias, float* __restrict__ C)
{
    extern __shared__ uint4 dyn[];
    uint4* sA = dyn;
    uint4* sB = dyn + 1024;

    const int tid    = threadIdx.x;
    const int lane   = tid & 31;
    const int wid    = tid >> 5;
    const int nb     = blockIdx.x;
    const int mb     = blockIdx.y;
    const int warp_m = (wid >> 2);
    const int warp_n = (wid & 3);

    const uint4* Ab = g_actx_frag + (size_t)mb * KIT * 512;
    const uint4* Bb = (const uint4*)(g_wout_frag + (size_t)nb * KIT * 1024);

    float acc[4][4][4];
#pragma unroll
    for (int mi = 0; mi < 4; mi++)
#pragma unroll
        for (int ni = 0; ni < 4; ni++)
#pragma unroll
            for (int r = 0; r < 4; r++) acc[mi][ni][r] = 0.f;

#pragma unroll
    for (int i = 0; i < 2; i++) {
        cp_async16(&sA[tid + i * 256], Ab + tid + i * 256);
        cp_async16(&sB[tid + i * 256], Bb + tid + i * 256);
    }
    cp_commit();

    for (int it = 0; it < KIT; it++) {
        const int buf = it & 1;
        if (it + 1 < KIT) {
            const int nbuf = (it + 1) & 1;
            const uint4* na  = Ab + (size_t)(it + 1) * 512;
            const uint4* nb4 = Bb + (size_t)(it + 1) * 512;
#pragma unroll
            for (int i = 0; i < 2; i++) {
                cp_async16(&sA[nbuf * 512 + tid + i * 256], na + tid + i * 256);
                cp_async16(&sB[nbuf * 512 + tid + i * 256], nb4 + tid + i * 256);
            }
            cp_commit();
            cp_wait<1>();
        } else {
            cp_wait<0>();
        }
        __syncthreads();

        const uint4* bA = sA + buf * 512;
        const uint2* bB = (const uint2*)(sB + buf * 512);

#pragma unroll
        for (int ks = 0; ks < 2; ks++) {
            uint4 ah[4]; uint2 bbv[4];
#pragma unroll
            for (int mi = 0; mi < 4; mi++)
                ah[mi] = bA[(ks * 8 + warp_m * 4 + mi) * 32 + lane];
#pragma unroll
            for (int ni = 0; ni < 4; ni++)
                bbv[ni] = bB[(ks * 16 + warp_n * 4 + ni) * 32 + lane];
#pragma unroll
            for (int mi = 0; mi < 4; mi++) {
                const uint32_t* ap = (const uint32_t*)&ah[mi];
#pragma unroll
                for (int ni = 0; ni < 4; ni++) {
                    uint32_t bfr[2] = {bbv[ni].x, bbv[ni].y};
                    mma_f16(acc[mi][ni], ap, bfr);
                }
            }
        }
        __syncthreads();
    }

    const int bm = mb * 128;
    const int bn = nb * 128;
#pragma unroll
    for (int mi = 0; mi < 4; mi++) {
        const int row = bm + warp_m * 64 + mi * 16 + (lane >> 2);
#pragma unroll
        for (int ni = 0; ni < 4; ni++) {
            const int col = bn + warp_n * 32 + ni * 8 + (lane & 3) * 2;
            const float2 bv2 = *(const float2*)&bias[col];
            float2 o0, o1;
            o0.x = acc[mi][ni][0] + bv2.x;  o0.y = acc[mi][ni][1] + bv2.y;
            o1.x = acc[mi][ni][2] + bv2.x;  o1.y = acc[mi][ni][3] + bv2.y;
            *(float2*)&C[(size_t)row * DMODEL + col]       = o0;
            *(float2*)&C[(size_t)(row + 8) * DMODEL + col] = o1;
        }
    }
}

// ---------------------------------------------------------------------------
// Tensor-core flash attention with fast-path (all-valid) tiles.
// Grid (24, 32): x<16 attention; x>=16 W_out presplit.
// ---------------------------------------------------------------------------
__global__ void __launch_bounds__(256, 2) attn_tc_kernel(
    const unsigned int* __restrict__ mask, const float* __restrict__ W_out)
{
    extern __shared__ uint4 dyn[];

    if (blockIdx.x >= 16) {
        const int nb2 = blockIdx.x - 16;
        const int it2 = blockIdx.y;
        uint2* chunk = g_wout_frag + ((size_t)nb2 * KIT + it2) * 1024;
#pragma unroll
        for (int i = 0; i < 4; i++) {
            const int s    = threadIdx.x + i * 256;
            const int lane = s & 31;
            const int n8   = (s >> 5) & 15;
            const int ks   = s >> 9;
            const int n = nb2 * 128 + n8 * 8 + (lane >> 2);
            const int k = it2 * 32 + ks * 16 + (lane & 3) * 2;
            const float b0 = W_out[(size_t)k * DMODEL + n];
            const float b1 = W_out[(size_t)(k + 1) * DMODEL + n];
            const float b2 = W_out[(size_t)(k + 8) * DMODEL + n];
            const float b3 = W_out[(size_t)(k + 9) * DMODEL + n];
            chunk[s] = make_uint2(pack2h(b0, b1), pack2h(b2, b3));
        }
        return;
    }

    uint4*    sK    = dyn;
    uint4*    sV    = dyn + 1024;
    uint32_t* sMask = (uint32_t*)(dyn + 2048);   // 2 x 64 words
    int*      sFlag = (int*)(dyn + 2048) + 128;  // 32 flags

    const int tid  = threadIdx.x;
    const int w    = tid >> 5;
    const int lane = tid & 31;
    const int bxr  = (S_LEN / 128 - 1) - blockIdx.x;
    const int bh   = blockIdx.y;
    const int b    = bh >> 4;
    const int h    = bh & 15;
    const int r0   = bxr * 128;

    const unsigned int* mb = mask + b * S_LEN;
    const uint4* kfb = (const uint4*)(g_kfrag + ((size_t)bh * NKTILES << 10));
    const uint4* vfb = (const uint4*)(g_vfrag + ((size_t)bh * NKTILES << 10));

    const int ntiles = (r0 + 128) >> 6;

    uint32_t qh[4][4];
    {
        const uint4* qc = g_qfrag + ((size_t)(b * 16 + bxr) * KIT) * 512;
#pragma unroll
        for (int ks = 0; ks < 4; ks++) {
            const int itq = h * 2 + (ks >> 1);
            const uint4 v = qc[(size_t)itq * 512 + ((ks & 1) * 8 + w) * 32 + lane];
            qh[ks][0] = v.x;  qh[ks][1] = v.y;
            qh[ks][2] = v.z;  qh[ks][3] = v.w;
        }
    }

    const uint32_t ONES2 = 0x3C003C00u;
    uint32_t onesb[2] = {ONES2, ONES2};
    float l_acc[4] = {0.f, 0.f, 0.f, 0.f};
    float o_acc[8][4];
#pragma unroll
    for (int dt = 0; dt < 8; dt++)
#pragma unroll
        for (int r = 0; r < 4; r++) o_acc[dt][r] = 0.f;

    const int q0g = r0 + w * 16 + (lane >> 2);

    if (tid < NKTILES) sFlag[tid] = g_maskall[b * NKTILES + tid];
    {
#pragma unroll
        for (int i = 0; i < 2; i++) {
            cp_async16(&sK[tid + i * 256], kfb + tid + i * 256);
            cp_async16(&sV[tid + i * 256], vfb + tid + i * 256);
        }
        if (tid < 16) cp_async16(&sMask[tid * 4], mb + tid * 4);
        cp_commit();
    }

    for (int t = 0; t < ntiles; t++) {
        const int buf = t & 1;
        if (t + 1 < ntiles) {
            const int nb = (t + 1) & 1;
            const uint4* srcK = kfb + ((size_t)(t + 1) << 9);
            const uint4* srcV = vfb + ((size_t)(t + 1) << 9);
#pragma unroll
            for (int i = 0; i < 2; i++) {
                cp_async16(&sK[nb * 512 + tid + i * 256], srcK + tid + i * 256);
                cp_async16(&sV[nb * 512 + tid + i * 256], srcV + tid + i * 256);
            }
            if (tid < 16) cp_async16(&sMask[nb * 64 + tid * 4], mb + (t + 1) * 64 + tid * 4);
            cp_commit();
            cp_wait<1>();
        } else {
            cp_wait<0>();
        }
        __syncthreads();

        const int k0 = t << 6;
        const uint2* bK = (const uint2*)(sK + buf * 512);
        const uint2* bV = (const uint2*)(sV + buf * 512);
        const uint32_t* bM = sMask + buf * 64;

        float s[8][4];
#pragma unroll
        for (int nt = 0; nt < 8; nt++)
#pragma unroll
            for (int r = 0; r < 4; r++) s[nt][r] = 0.f;

#pragma unroll
        for (int ks = 0; ks < 4; ks++) {
#pragma unroll
            for (int nt = 0; nt < 8; nt++) {
                const uint2 v = bK[(nt * 4 + ks) * 32 + lane];
                uint32_t bfr[2] = {v.x, v.y};
                mma_f16(s[nt], qh[ks], bfr);
            }
        }

        // fast path: tile fully causal for this warp AND padding all-set
        const bool fast = (k0 + 63 <= r0 + w * 16) && sFlag[t];
        if (!fast) {
#pragma unroll
            for (int nt = 0; nt < 8; nt++)
#pragma unroll
                for (int r = 0; r < 4; r++) {
                    const int row = r >> 1;
                    const int c   = r & 1;
                    const int kl  = nt * 8 + (lane & 3) * 2 + c;
                    const bool ok = (bM[kl] != 0u) && (k0 + kl <= q0g + row * 8);
                    s[nt][r] = ok ? s[nt][r] : -1e9f;
                }
        }

#pragma unroll
        for (int ks2 = 0; ks2 < 4; ks2++) {
            uint32_t pah[4];
            pah[0] = exp2_h2(pack2h(s[ks2*2][0],   s[ks2*2][1]));
            pah[1] = exp2_h2(pack2h(s[ks2*2][2],   s[ks2*2][3]));
            pah[2] = exp2_h2(pack2h(s[ks2*2+1][0], s[ks2*2+1][1]));
            pah[3] = exp2_h2(pack2h(s[ks2*2+1][2], s[ks2*2+1][3]));
            mma_f16(l_acc, pah, onesb);
#pragma unroll
            for (int dt = 0; dt < 8; dt++) {
                const uint2 v = bV[(dt * 4 + ks2) * 32 + lane];
                uint32_t bfr[2] = {v.x, v.y};
                mma_f16(o_acc[dt], pah, bfr);
            }
        }
        __syncthreads();
    }

    const float inv0 = 1.f / l_acc[0];
    const float inv1 = 1.f / l_acc[2];
    uint4* dst = g_actx_frag + ((size_t)(b * 16 + (r0 >> 7)) * KIT) * 512;
#pragma unroll
    for (int f = 0; f < 4; f++) {
        const int it  = h * 2 + (f >> 1);
        const int ks  = f & 1;
        const int dt0 = f * 2, dt1 = f * 2 + 1;
        uint4 u;
        u.x = pack2h(o_acc[dt0][0] * inv0, o_acc[dt0][1] * inv0);
        u.y = pack2h(o_acc[dt0][2] * inv1, o_acc[dt0][3] * inv1);
        u.z = pack2h(o_acc[dt1][0] * inv0, o_acc[dt1][1] * inv0);
        u.w = pack2h(o_acc[dt1][2] * inv1, o_acc[dt1][3] * inv1);
        dst[(size_t)it * 512 + (ks * 8 + w) * 32 + lane] = u;
    }
}

// ---------------------------------------------------------------------------
extern "C" void kernel_launch(void* const* d_in, const int* in_sizes, int n_in,
                              void* d_out, int out_size)
{
    const float*        tokens = (const float*)d_in[0];
    const unsigned int* mask   = (const unsigned int*)d_in[1];
    const int*          seqc   = (const int*)d_in[2];
    const float*        W_qkv  = (const float*)d_in[3];
    const float*        b_qkv  = (const float*)d_in[4];
    const float*        Wq     = (const float*)d_in[5];
    const float*        bq     = (const float*)d_in[6];
    const float*        Wk     = (const float*)d_in[7];
    const float*        bk     = (const float*)d_in[8];
    const float*        Wv     = (const float*)d_in[9];
    const float*        bv     = (const float*)d_in[10];
    const float*        W_out  = (const float*)d_in[11];
    const float*        b_out  = (const float*)d_in[12];
    float*              out    = (float*)d_out;

    cudaFuncSetAttribute(gemm_qkv_kernel,
                         cudaFuncAttributeMaxDynamicSharedMemorySize, 32768);
    cudaFuncSetAttribute(gemm_out_kernel,
                         cudaFuncAttributeMaxDynamicSharedMemorySize, 32768);
    cudaFuncSetAttribute(attn_tc_kernel,
                         cudaFuncAttributeMaxDynamicSharedMemorySize, 33536);

    // 1) presplit: W_qkv + tokens + mask tile flags
    presplit_all_kernel<<<1793, 256>>>(tokens, W_qkv, mask);

    // 2) QKV projection + fused Q/K/V frag emission + fused ns blocks
    gemm_qkv_kernel<<<816, 256, 32768>>>(b_qkv, tokens, seqc,
                                         Wq, bq, Wk, bk, Wv, bv);

    // 3) attention (+ W_out presplit riding the grid)
    dim3 g2(24, BATCH * NHEADS);
    attn_tc_kernel<<<g2, 256, 33536>>>(mask, W_out);

    // 4) output projection -> d_out
    dim3 g3(DMODEL / 128, MBLK);
    gemm_out_kernel<<<g3, 256, 32768>>>(b_out, out);
}